// round 14
// baseline (speedup 1.0000x reference)
#include <cuda_runtime.h>
#include <cuda_fp16.h>
#include <mma.h>
#include <math.h>

using namespace nvcuda;

#define N_NODES   50000
#define N_PAD     50048
#define N_EDGES   800000
#define HIDDEN    128
#define NUM_GRAPHS 256
#define GPAD      136
#define SCAN_BLKS 196            // ceil(50000/256)

// ---------------- scratch (device globals) ----------------------------------
__device__ float  g_h[N_NODES * HIDDEN];
__device__ float  g_agg[N_NODES * HIDDEN];
__device__ __half g_hhi[N_NODES * HIDDEN];
__device__ __half g_hlo[N_NODES * HIDDEN];
__device__ __half g_A[(size_t)N_PAD * 512];
__device__ __half g_Whi[2][128 * 512];
__device__ __half g_Wlo[2][128 * 512];
__device__ __half g_WT[2][256 * 32];
__device__ __half g_eh[(size_t)N_EDGES * 32];   // sorted fp16 edge attrs (51.2 MB)
__device__ float  g_gsum[NUM_GRAPHS * HIDDEN];
__device__ float  g_gcnt[NUM_GRAPHS];
// edge sort
__device__ int    g_cnt[N_NODES];
__device__ int    g_off[N_NODES];
__device__ int    g_blk[256];
__device__ int    g_perm[N_EDGES];
__device__ int    g_sdst[N_EDGES];
__device__ int    g_ssrc[N_EDGES];

// ---------------- helpers ------------------------------------------------------
__device__ __forceinline__ void red_v4(float* p, float a, float b, float c, float d) {
    asm volatile("red.global.add.v4.f32 [%0], {%1,%2,%3,%4};"
                 :: "l"(p), "f"(a), "f"(b), "f"(c), "f"(d) : "memory");
}
__device__ __forceinline__ float tanh_fast(float x) {
    float r; asm("tanh.approx.f32 %0, %1;" : "=f"(r) : "f"(x)); return r;
}
__device__ __forceinline__ float lg2_fast(float x) {
    float r; asm("lg2.approx.f32 %0, %1;" : "=f"(r) : "f"(x)); return r;
}
__device__ __forceinline__ float ex2_fast(float x) {
    float r; asm("ex2.approx.f32 %0, %1;" : "=f"(r) : "f"(x)); return r;
}
__device__ __forceinline__ unsigned smaddr(const void* p) {
    return (unsigned)__cvta_generic_to_shared(p);
}
#define CP16(dst, src) asm volatile("cp.async.cg.shared.global [%0], [%1], 16;" :: "r"(dst), "l"(src))
#define CP_COMMIT()    asm volatile("cp.async.commit_group;" ::: "memory")
#define CP_WAIT0()     asm volatile("cp.async.wait_group 0;" ::: "memory")

// ---------------- edge sort: histogram / scan / scatter -----------------------
__global__ __launch_bounds__(256) void hist_kernel(const int* __restrict__ dst) {
    int e = blockIdx.x * 256 + threadIdx.x;
    atomicAdd(&g_cnt[dst[e]], 1);
}
__global__ __launch_bounds__(256) void scan1_kernel() {
    __shared__ int s[256];
    int i = blockIdx.x * 256 + threadIdx.x;
    int v = (i < N_NODES) ? g_cnt[i] : 0;
    s[threadIdx.x] = v; __syncthreads();
#pragma unroll
    for (int o = 1; o < 256; o <<= 1) {
        int t = (threadIdx.x >= o) ? s[threadIdx.x - o] : 0;
        __syncthreads();
        s[threadIdx.x] += t;
        __syncthreads();
    }
    if (i < N_NODES) g_off[i] = s[threadIdx.x] - v;
    if (threadIdx.x == 255) g_blk[blockIdx.x] = s[255];
}
__global__ __launch_bounds__(256) void scan2_kernel() {
    __shared__ int s[256];
    int v = (threadIdx.x < SCAN_BLKS) ? g_blk[threadIdx.x] : 0;
    s[threadIdx.x] = v; __syncthreads();
#pragma unroll
    for (int o = 1; o < 256; o <<= 1) {
        int t = (threadIdx.x >= o) ? s[threadIdx.x - o] : 0;
        __syncthreads();
        s[threadIdx.x] += t;
        __syncthreads();
    }
    g_blk[threadIdx.x] = s[threadIdx.x] - v;
}
__global__ __launch_bounds__(256) void scan3_kernel() {
    int i = blockIdx.x * 256 + threadIdx.x;
    if (i < N_NODES) {
        int o = g_off[i] + g_blk[blockIdx.x];
        g_off[i] = o;
        g_cnt[i] = o;
    }
}
__global__ __launch_bounds__(256) void scatter_kernel(
    const int* __restrict__ dst, const int* __restrict__ src) {
    int e = blockIdx.x * 256 + threadIdx.x;
    int d = dst[e];
    int slot = atomicAdd(&g_cnt[d], 1);
    g_sdst[slot] = d;
    g_ssrc[slot] = src[e];
    g_perm[slot] = e;
}
// convert eattr to fp16 in sorted order (4 threads per edge row)
__global__ __launch_bounds__(256) void econv_kernel(const float4* __restrict__ eattr) {
    int gi = blockIdx.x * 256 + threadIdx.x;       // 3.2M
    int s = gi >> 2, q = gi & 3;
    int pe = g_perm[s];
    float4 a = __ldcs(eattr + (size_t)pe * 8 + q * 2);
    float4 b = __ldcs(eattr + (size_t)pe * 8 + q * 2 + 1);
    uint4 o;
    __half2 h0 = __floats2half2_rn(a.x, a.y);
    __half2 h1 = __floats2half2_rn(a.z, a.w);
    __half2 h2 = __floats2half2_rn(b.x, b.y);
    __half2 h3 = __floats2half2_rn(b.z, b.w);
    o.x = *(unsigned*)&h0; o.y = *(unsigned*)&h1;
    o.z = *(unsigned*)&h2; o.w = *(unsigned*)&h3;
    ((uint4*)g_eh)[(size_t)s * 4 + q] = o;
}

// ---------------- conv1: CGConv(C=3, edge=32) -------------------------------
__global__ __launch_bounds__(256) void conv1_kernel(
    const float* __restrict__ x, const int* __restrict__ src, const int* __restrict__ dst,
    const float* __restrict__ eattr,
    const float* __restrict__ Wf, const float* __restrict__ bf,
    const float* __restrict__ Ws, const float* __restrict__ bs,
    float* __restrict__ agg)
{
    __shared__ float wf[38 * 3], ws[38 * 3], bfs[3], bss[3];
    int tid = threadIdx.x;
    if (tid < 114) { wf[tid] = Wf[tid]; ws[tid] = Ws[tid]; }
    if (tid < 3)   { bfs[tid] = bf[tid]; bss[tid] = bs[tid]; }
    __syncthreads();

    int e = blockIdx.x * 256 + tid;
    int d  = dst[e];
    int sn = src[e];

    float f[3], s[3];
#pragma unroll
    for (int j = 0; j < 3; j++) { f[j] = bfs[j]; s[j] = bss[j]; }

#pragma unroll
    for (int i = 0; i < 3; i++) {
        float xd = x[d * 3 + i];
        float xs = x[sn * 3 + i];
#pragma unroll
        for (int j = 0; j < 3; j++) {
            f[j] += xd * wf[i * 3 + j];
            s[j] += xd * ws[i * 3 + j];
            f[j] += xs * wf[(3 + i) * 3 + j];
            s[j] += xs * ws[(3 + i) * 3 + j];
        }
    }
    const float4* ep = (const float4*)(eattr + (size_t)e * 32);
#pragma unroll
    for (int q = 0; q < 8; q++) {
        float4 v = ep[q];
        float ev[4] = {v.x, v.y, v.z, v.w};
#pragma unroll
        for (int r = 0; r < 4; r++) {
            int k = 6 + q * 4 + r;
#pragma unroll
            for (int j = 0; j < 3; j++) {
                f[j] += ev[r] * wf[k * 3 + j];
                s[j] += ev[r] * ws[k * 3 + j];
            }
        }
    }
#pragma unroll
    for (int j = 0; j < 3; j++) {
        float sg = 0.5f + 0.5f * tanh_fast(0.5f * f[j]);
        float sp = fmaxf(s[j], 0.f) + __logf(1.f + __expf(-fabsf(s[j])));
        atomicAdd(agg + (size_t)d * 3 + j, sg * sp);
    }
}

// ---------------- node projection (+ fused fp16 split) ------------------------
__global__ __launch_bounds__(256) void proj_kernel(
    const float* __restrict__ x, const float* __restrict__ agg1,
    const float* __restrict__ Wp, const float* __restrict__ bp,
    float* __restrict__ h, __half* __restrict__ hhi, __half* __restrict__ hlo)
{
    int idx = blockIdx.x * 256 + threadIdx.x;
    int n = idx >> 7, c = idx & 127;
    float v = bp[c];
#pragma unroll
    for (int i = 0; i < 3; i++)
        v += (x[n * 3 + i] + agg1[n * 3 + i]) * Wp[i * 128 + c];
    v = fmaxf(v, 0.f);
    h[idx] = v;
    __half hi = __float2half(v);
    hhi[idx] = hi;
    hlo[idx] = __float2half(v - __half2float(hi));
}

// ---------------- weight pack ---------------------------------------------------
__global__ __launch_bounds__(256) void pack_kernel(
    const float* __restrict__ Wf, const float* __restrict__ Ws,
    __half* __restrict__ Whi, __half* __restrict__ Wlo, __half* __restrict__ WT)
{
    int idx = blockIdx.x * 256 + threadIdx.x;
    {
        int k = idx >> 9;
        int j = idx & 511;
        int role = j >> 8;
        int c = (j & 255) >> 1;
        int gate = j & 1;
        const float* G = gate ? Ws : Wf;
        float v = G[(role * 128 + k) * 128 + c];
        __half hi = __float2half(v);
        Whi[idx] = hi;
        Wlo[idx] = __float2half(v - __half2float(hi));
    }
    if (idx < 256 * 32) {
        int g = idx >> 5;
        int k = idx & 31;
        int c = g >> 1;
        int gate = g & 1;
        const float* G = gate ? Ws : Wf;
        WT[idx] = __float2half(G[(256 + k) * 128 + c]);
    }
}

// ---------------- node GEMM via split-fp16 wmma ------------------------------
__global__ __launch_bounds__(512) void gemm_node(
    const __half* __restrict__ Hhi, const __half* __restrict__ Hlo,
    const __half* __restrict__ Whi, const __half* __restrict__ Wlo,
    __half* __restrict__ A)
{
    extern __shared__ __half sm[];
    __half (*hh)[GPAD] = (__half(*)[GPAD])sm;
    __half (*hl)[GPAD] = hh + 128;
    __half (*wh)[GPAD] = hl + 128;
    __half (*wl)[GPAD] = wh + 128;

    int tid = threadIdx.x;
    int bm = blockIdx.x * 128;
    int bn = blockIdx.y * 128;

#pragma unroll
    for (int t = 0; t < 4; t++) {
        int li = tid + t * 512;
        int row = li >> 4, q = li & 15;
        int rg = bm + row; if (rg > N_NODES - 1) rg = N_NODES - 1;
        CP16(smaddr(&hh[row][q * 8]), Hhi + (size_t)rg * 128 + q * 8);
        CP16(smaddr(&hl[row][q * 8]), Hlo + (size_t)rg * 128 + q * 8);
        CP16(smaddr(&wh[row][q * 8]), Whi + (size_t)row * 512 + bn + q * 8);
        CP16(smaddr(&wl[row][q * 8]), Wlo + (size_t)row * 512 + bn + q * 8);
    }
    CP_COMMIT();
    CP_WAIT0();
    __syncthreads();

    int w  = tid >> 5;
    int mw = w & 7;
    int nh = w >> 3;
    int m0 = mw * 16;

#pragma unroll
    for (int t = 0; t < 4; t++) {
        int n0 = (nh * 4 + t) * 16;
        wmma::fragment<wmma::accumulator, 16, 16, 16, float> acc;
        wmma::fill_fragment(acc, 0.f);
#pragma unroll
        for (int k = 0; k < 8; k++) {
            wmma::fragment<wmma::matrix_a, 16, 16, 16, __half, wmma::row_major> ah, al;
            wmma::fragment<wmma::matrix_b, 16, 16, 16, __half, wmma::row_major> bh, bl;
            wmma::load_matrix_sync(ah, &hh[m0][k * 16], GPAD);
            wmma::load_matrix_sync(al, &hl[m0][k * 16], GPAD);
            wmma::load_matrix_sync(bh, &wh[k * 16][n0], GPAD);
            wmma::load_matrix_sync(bl, &wl[k * 16][n0], GPAD);
            wmma::mma_sync(acc, ah, bh, acc);
            wmma::mma_sync(acc, ah, bl, acc);
            wmma::mma_sync(acc, al, bh, acc);
        }
        wmma::fragment<wmma::accumulator, 16, 16, 16, __half> hacc;
#pragma unroll
        for (int i = 0; i < acc.num_elements; i++) hacc.x[i] = __float2half(acc.x[i]);
        wmma::store_matrix_sync(A + (size_t)(bm + m0) * 512 + bn + n0,
                                hacc, 512, wmma::mem_row_major);
    }
}

// ---- fused CGConv edge kernel (sorted fp16 eattr, lazy dst, run-combined) ----
__global__ __launch_bounds__(256) void edge_kernel(
    const int* __restrict__ sdst, const int* __restrict__ ssrc,
    const __half* __restrict__ eh,
    const __half* __restrict__ WT,
    const float* __restrict__ bf, const float* __restrict__ bs,
    const uint4* __restrict__ A4, float* __restrict__ agg)
{
    extern __shared__ char smc[];
    __half (*Es)[32]   = (__half(*)[32])smc;                        // 4 KB
    __half (*WTs)[32]  = (__half(*)[32])(smc + 4096);               // 16 KB
    __half (*Ew)[256]  = (__half(*)[256])(smc + 4096 + 16384);      // 32 KB
    int2*  di          = (int2*)(smc + 4096 + 16384 + 32768);       // 512 B

    int tid = threadIdx.x;
    int w   = tid >> 5;
    int l   = tid & 31;
    int ebase = blockIdx.x * 64;

    if (tid < 64) di[tid] = make_int2(sdst[ebase + tid], ssrc[ebase + tid]);
    // fp16 edge attrs: 64 edges * 64 B = 256 uint4, one per thread
    ((uint4*)Es)[tid] = ((const uint4*)(eh + (size_t)ebase * 32))[tid];
    {   // gate weights
        const uint4* wsrc = (const uint4*)WT;
        uint4* wdst = (uint4*)WTs;
#pragma unroll
        for (int t = 0; t < 4; t++)
            wdst[tid + t * 256] = wsrc[tid + t * 256];
    }
    __syncthreads();

    // phase 1: Ew[64][256] = Es @ WT^T  (wmma, fp32 accum)
    {
        int mt = w & 3;
        int nb = (w >> 2) * 8;
        wmma::fragment<wmma::matrix_a, 16, 16, 16, __half, wmma::row_major> a0, a1;
        wmma::load_matrix_sync(a0, &Es[mt * 16][0], 32);
        wmma::load_matrix_sync(a1, &Es[mt * 16][16], 32);
#pragma unroll
        for (int t = 0; t < 8; t++) {
            int nt = nb + t;
            wmma::fragment<wmma::accumulator, 16, 16, 16, float> acc;
            wmma::fill_fragment(acc, 0.f);
            wmma::fragment<wmma::matrix_b, 16, 16, 16, __half, wmma::col_major> b0, b1;
            wmma::load_matrix_sync(b0, &WTs[nt * 16][0], 32);
            wmma::load_matrix_sync(b1, &WTs[nt * 16][16], 32);
            wmma::mma_sync(acc, a0, b0, acc);
            wmma::mma_sync(acc, a1, b1, acc);
            wmma::fragment<wmma::accumulator, 16, 16, 16, __half> hacc;
#pragma unroll
            for (int i = 0; i < acc.num_elements; i++) hacc.x[i] = __float2half(acc.x[i]);
            wmma::store_matrix_sync(&Ew[mt * 16][nt * 16], hacc, 256, wmma::mem_row_major);
        }
    }
    __syncthreads();

    // phase 2: warp-per-edge; per-run fp32 base (bias+dst, half-scaled f part)
    float4 bf4 = *(const float4*)(bf + 4 * l);
    float4 bs4 = *(const float4*)(bs + 4 * l);
    const float* bfp = (const float*)&bf4;
    const float* bsp = (const float*)&bs4;
    int e0 = w * 8;

    uint4 ps[4];
#pragma unroll
    for (int i = 0; i < 4; i++)
        ps[i] = __ldg(A4 + (size_t)di[e0 + i].y * 64 + 32 + l);

    int cur = di[e0].x;
    float bfd[4], bsd[4];
    {
        uint4 rd = __ldg(A4 + (size_t)cur * 64 + l);
        const __half2* hd = (const __half2*)&rd;
#pragma unroll
        for (int j = 0; j < 4; j++) {
            float2 t = __half22float2(hd[j]);
            bfd[j] = 0.5f * (bfp[j] + t.x);   // pre-scaled for tanh(f/2)
            bsd[j] = bsp[j] + t.y;
        }
    }
    float facc[4] = {0.f, 0.f, 0.f, 0.f};

#pragma unroll
    for (int i = 0; i < 8; i++) {
        int b = i & 3;
        uint4 rs = ps[b];
        if (i < 4)
            ps[b] = __ldg(A4 + (size_t)di[e0 + i + 4].y * 64 + 32 + l);

        int d = di[e0 + i].x;
        if (d != cur) {                       // warp-uniform
            red_v4(agg + (size_t)cur * 128 + 4 * l, facc[0], facc[1], facc[2], facc[3]);
            cur = d;
            uint4 rd = __ldg(A4 + (size_t)cur * 64 + l);
            const __half2* hd = (const __half2*)&rd;
#pragma unroll
            for (int j = 0; j < 4; j++) {
                float2 t = __half22float2(hd[j]);
                bfd[j] = 0.5f * (bfp[j] + t.x);
                bsd[j] = bsp[j] + t.y;
                facc[j] = 0.f;
            }
        }

        uint4 ewv = *(uint4*)&Ew[e0 + i][8 * l];
        const __half2* hsv = (const __half2*)&rs;
        const __half2* he  = (const __half2*)&ewv;
#pragma unroll
        for (int j = 0; j < 4; j++) {
            __half2 sum = __hadd2(hsv[j], he[j]);      // src + edge gate (fp16)
            float2 t = __half22float2(sum);
            float fa = fmaf(t.x, 0.5f, bfd[j]);        // (f)/2
            float th = tanh_fast(fa);                  // 2σ(f)-1
            float s  = bsd[j] + t.y;
            float em = ex2_fast(-1.442695041f * fabsf(s));
            float l2 = lg2_fast(1.f + em);
            float sp = fmaf(l2, 0.6931471806f, fmaxf(s, 0.f));
            float tmp = fmaf(th, sp, sp);              // (1+th)·sp
            facc[j] = fmaf(tmp, 0.5f, facc[j]);        // += σ(f)·sp
        }
    }
    red_v4(agg + (size_t)cur * 128 + 4 * l, facc[0], facc[1], facc[2], facc[3]);
}

// ---------------- h = relu(h + agg) + fused fp16 split ------------------------
__global__ __launch_bounds__(256) void relu_add_kernel(
    float4* __restrict__ h, const float4* __restrict__ agg,
    __half2* __restrict__ hhi, __half2* __restrict__ hlo)
{
    int idx = blockIdx.x * 256 + threadIdx.x;
    float4 a = h[idx], b = agg[idx];
    a.x = fmaxf(a.x + b.x, 0.f);
    a.y = fmaxf(a.y + b.y, 0.f);
    a.z = fmaxf(a.z + b.z, 0.f);
    a.w = fmaxf(a.w + b.w, 0.f);
    h[idx] = a;
    __half hx = __float2half(a.x), hy = __float2half(a.y);
    __half hz = __float2half(a.z), hw = __float2half(a.w);
    hhi[idx * 2 + 0] = __halves2half2(hx, hy);
    hhi[idx * 2 + 1] = __halves2half2(hz, hw);
    hlo[idx * 2 + 0] = __halves2half2(__float2half(a.x - __half2float(hx)),
                                      __float2half(a.y - __half2float(hy)));
    hlo[idx * 2 + 1] = __halves2half2(__float2half(a.z - __half2float(hz)),
                                      __float2half(a.w - __half2float(hw)));
}

// ---------------- final relu + mean pool fused (vector RED) -------------------
__global__ __launch_bounds__(256) void relu_pool_kernel(
    const float4* __restrict__ h, const float4* __restrict__ agg,
    const int* __restrict__ batch,
    float* __restrict__ gsum, float* __restrict__ gcnt)
{
    int idx = blockIdx.x * 256 + threadIdx.x;
    int n = idx >> 5, q = idx & 31;
    float4 a = h[idx], b = agg[idx];
    a.x = fmaxf(a.x + b.x, 0.f);
    a.y = fmaxf(a.y + b.y, 0.f);
    a.z = fmaxf(a.z + b.z, 0.f);
    a.w = fmaxf(a.w + b.w, 0.f);
    int g = batch[n];
    red_v4(gsum + (size_t)g * 128 + 4 * q, a.x, a.y, a.z, a.w);
    if (q == 0) atomicAdd(gcnt + g, 1.f);
}

// ---------------- final MLP ---------------------------------------------------
__global__ __launch_bounds__(128) void final_kernel(
    const float* __restrict__ gsum, const float* __restrict__ gcnt,
    const float* __restrict__ W1, const float* __restrict__ b1,
    const float* __restrict__ Wh, const float* __restrict__ bh,
    float* __restrict__ out)
{
    __shared__ float mean[128];
    __shared__ float ga[128];
    int g = blockIdx.x;
    int c = threadIdx.x;
    float cnt = fmaxf(gcnt[g], 1.f);
    mean[c] = gsum[(size_t)g * 128 + c] / cnt;
    __syncthreads();
    float acc = b1[c];
#pragma unroll 8
    for (int k = 0; k < 128; k++)
        acc += mean[k] * W1[k * 128 + c];
    ga[c] = fmaxf(acc, 0.f);
    __syncthreads();
    if (c < 5) {
        float o = bh[c];
#pragma unroll 8
        for (int k = 0; k < 128; k++)
            o += ga[k] * Wh[c * 128 + k];
        out[g * 5 + c] = o;
    }
}

// =============================================================================
extern "C" void kernel_launch(void* const* d_in, const int* in_sizes, int n_in,
                              void* d_out, int out_size)
{
    const float* x        = (const float*)d_in[0];
    const int*   eidx     = (const int*)  d_in[1];
    const float* eattr    = (const float*)d_in[2];
    const int*   batch    = (const int*)  d_in[3];
    const float* Wf1      = (const float*)d_in[4];
    const float* bf1      = (const float*)d_in[5];
    const float* Ws1      = (const float*)d_in[6];
    const float* bs1      = (const float*)d_in[7];
    const float* Wp       = (const float*)d_in[8];
    const float* bp       = (const float*)d_in[9];
    const float* Wf_convs = (const float*)d_in[10];
    const float* bf_convs = (const float*)d_in[11];
    const float* Ws_convs = (const float*)d_in[12];
    const float* bs_convs = (const float*)d_in[13];
    const float* W1       = (const float*)d_in[14];
    const float* b1       = (const float*)d_in[15];
    const float* Wh       = (const float*)d_in[16];
    const float* bh       = (const float*)d_in[17];
    float* out = (float*)d_out;

    const int* srcp = eidx;
    const int* dstp = eidx + N_EDGES;

    float *p_h, *p_agg, *p_gsum, *p_gcnt;
    __half *p_hhi, *p_hlo, *p_A, *p_Whi, *p_Wlo, *p_WT, *p_eh;
    int *p_cnt, *p_sdst, *p_ssrc;
    cudaGetSymbolAddress((void**)&p_h,    g_h);
    cudaGetSymbolAddress((void**)&p_agg,  g_agg);
    cudaGetSymbolAddress((void**)&p_hhi,  g_hhi);
    cudaGetSymbolAddress((void**)&p_hlo,  g_hlo);
    cudaGetSymbolAddress((void**)&p_A,    g_A);
    cudaGetSymbolAddress((void**)&p_Whi,  g_Whi);
    cudaGetSymbolAddress((void**)&p_Wlo,  g_Wlo);
    cudaGetSymbolAddress((void**)&p_WT,   g_WT);
    cudaGetSymbolAddress((void**)&p_eh,   g_eh);
    cudaGetSymbolAddress((void**)&p_gsum, g_gsum);
    cudaGetSymbolAddress((void**)&p_gcnt, g_gcnt);
    cudaGetSymbolAddress((void**)&p_cnt,  g_cnt);
    cudaGetSymbolAddress((void**)&p_sdst, g_sdst);
    cudaGetSymbolAddress((void**)&p_ssrc, g_ssrc);

    static cudaStream_t s2 = nullptr;
    static cudaEvent_t ev_root = nullptr, ev_pack = nullptr, ev_sort = nullptr;
    static cudaEvent_t ev_proj = nullptr, ev_ms0 = nullptr, ev_ra = nullptr, ev_ms1 = nullptr;
    static int smem_cfg = 0;
    if (!smem_cfg) {
        cudaFuncSetAttribute(edge_kernel, cudaFuncAttributeMaxDynamicSharedMemorySize, 54272);
        cudaFuncSetAttribute(gemm_node, cudaFuncAttributeMaxDynamicSharedMemorySize, 4 * 128 * GPAD * 2);
        cudaStreamCreateWithFlags(&s2, cudaStreamNonBlocking);
        cudaEventCreateWithFlags(&ev_root, cudaEventDisableTiming);
        cudaEventCreateWithFlags(&ev_pack, cudaEventDisableTiming);
        cudaEventCreateWithFlags(&ev_sort, cudaEventDisableTiming);
        cudaEventCreateWithFlags(&ev_proj, cudaEventDisableTiming);
        cudaEventCreateWithFlags(&ev_ms0,  cudaEventDisableTiming);
        cudaEventCreateWithFlags(&ev_ra,   cudaEventDisableTiming);
        cudaEventCreateWithFlags(&ev_ms1,  cudaEventDisableTiming);
        smem_cfg = 1;
    }

    const int EB  = N_EDGES / 256;                    // 3125
    const int NB  = (N_NODES * HIDDEN) / 256;         // 25000
    const int NB4 = (N_NODES * HIDDEN / 4) / 256;     // 6250
    const int EB2 = N_EDGES / 64;                     // 12500
    const size_t WWSZ = (size_t)128 * 512;
    const size_t WTSZ = (size_t)256 * 32;

    // ---- fork to s2: pack weights, sort chain, fp16 eattr, small memsets ----
    cudaEventRecord(ev_root, 0);
    cudaStreamWaitEvent(s2, ev_root, 0);
    for (int l = 0; l < 2; l++) {
        pack_kernel<<<(128 * 512) / 256, 256, 0, s2>>>(
            Wf_convs + (size_t)l * 288 * 128, Ws_convs + (size_t)l * 288 * 128,
            p_Whi + l * WWSZ, p_Wlo + l * WWSZ, p_WT + l * WTSZ);
    }
    cudaEventRecord(ev_pack, s2);
    cudaMemsetAsync(p_cnt, 0, N_NODES * sizeof(int), s2);
    cudaMemsetAsync(p_gsum, 0, (size_t)NUM_GRAPHS * HIDDEN * sizeof(float), s2);
    cudaMemsetAsync(p_gcnt, 0, (size_t)NUM_GRAPHS * sizeof(float), s2);
    hist_kernel<<<EB, 256, 0, s2>>>(dstp);
    scan1_kernel<<<SCAN_BLKS, 256, 0, s2>>>();
    scan2_kernel<<<1, 256, 0, s2>>>();
    scan3_kernel<<<SCAN_BLKS, 256, 0, s2>>>();
    scatter_kernel<<<EB, 256, 0, s2>>>(dstp, srcp);
    econv_kernel<<<(N_EDGES * 4) / 256, 256, 0, s2>>>((const float4*)eattr);
    cudaEventRecord(ev_sort, s2);

    // ---- main: conv1 + projection ----
    cudaMemsetAsync(p_agg, 0, (size_t)N_NODES * 3 * sizeof(float));
    conv1_kernel<<<EB, 256>>>(x, srcp, dstp, eattr, Wf1, bf1, Ws1, bs1, p_agg);
    proj_kernel<<<NB, 256>>>(x, p_agg, Wp, bp, p_h, p_hhi, p_hlo);
    cudaEventRecord(ev_proj, 0);

    // agg memset for layer 0 on s2, overlapped with gemm l0
    cudaStreamWaitEvent(s2, ev_proj, 0);
    cudaMemsetAsync(p_agg, 0, (size_t)N_NODES * HIDDEN * sizeof(float), s2);
    cudaEventRecord(ev_ms0, s2);

    // ---- layer 0 ----
    cudaStreamWaitEvent(0, ev_pack, 0);
    dim3 gg(N_PAD / 128, 4);
    gemm_node<<<gg, 512, 4 * 128 * GPAD * 2>>>(p_hhi, p_hlo, p_Whi, p_Wlo, p_A);
    cudaStreamWaitEvent(0, ev_sort, 0);
    cudaStreamWaitEvent(0, ev_ms0, 0);
    edge_kernel<<<EB2, 256, 54272>>>(p_sdst, p_ssrc, p_eh,
                                     p_WT, bf_convs, bs_convs,
                                     (const uint4*)p_A, p_agg);
    relu_add_kernel<<<NB4, 256>>>((float4*)p_h, (const float4*)p_agg,
                                  (__half2*)p_hhi, (__half2*)p_hlo);
    cudaEventRecord(ev_ra, 0);

    // agg memset for layer 1 on s2, overlapped with gemm l1
    cudaStreamWaitEvent(s2, ev_ra, 0);
    cudaMemsetAsync(p_agg, 0, (size_t)N_NODES * HIDDEN * sizeof(float), s2);
    cudaEventRecord(ev_ms1, s2);

    // ---- layer 1 ----
    gemm_node<<<gg, 512, 4 * 128 * GPAD * 2>>>(p_hhi, p_hlo,
                                               p_Whi + WWSZ, p_Wlo + WWSZ, p_A);
    cudaStreamWaitEvent(0, ev_ms1, 0);
    edge_kernel<<<EB2, 256, 54272>>>(p_sdst, p_ssrc, p_eh,
                                     p_WT + WTSZ, bf_convs + 128, bs_convs + 128,
                                     (const uint4*)p_A, p_agg);
    relu_pool_kernel<<<NB4, 256>>>((const float4*)p_h, (const float4*)p_agg,
                                   batch, p_gsum, p_gcnt);

    final_kernel<<<NUM_GRAPHS, 128>>>(p_gsum, p_gcnt, W1, b1, Wh, bh, out);
}

// round 15
// speedup vs baseline: 1.0330x; 1.0330x over previous
#include <cuda_runtime.h>
#include <cuda_fp16.h>
#include <mma.h>
#include <math.h>

using namespace nvcuda;

#define N_NODES   50000
#define N_PAD     50048
#define N_EDGES   800000
#define HIDDEN    128
#define NUM_GRAPHS 256
#define GPAD      136
#define SCAN_BLKS 196            // ceil(50000/256)

// ---------------- scratch (device globals) ----------------------------------
__device__ float  g_h[N_NODES * HIDDEN];
__device__ float  g_agg[N_NODES * HIDDEN];
__device__ __half g_hhi[N_NODES * HIDDEN];
__device__ __half g_hlo[N_NODES * HIDDEN];
__device__ __half g_A[(size_t)N_PAD * 512];
__device__ __half g_Whi[2][128 * 512];
__device__ __half g_Wlo[2][128 * 512];
__device__ __half g_WT[2][256 * 32];
__device__ float  g_gsum[NUM_GRAPHS * HIDDEN];
__device__ float  g_gcnt[NUM_GRAPHS];
// edge sort
__device__ int    g_cnt[N_NODES];
__device__ int    g_off[N_NODES];
__device__ int    g_blk[256];
__device__ int    g_perm[N_EDGES];
__device__ int    g_sdst[N_EDGES];
__device__ int    g_ssrc[N_EDGES];

// ---------------- helpers ------------------------------------------------------
__device__ __forceinline__ void red_v4(float* p, float a, float b, float c, float d) {
    asm volatile("red.global.add.v4.f32 [%0], {%1,%2,%3,%4};"
                 :: "l"(p), "f"(a), "f"(b), "f"(c), "f"(d) : "memory");
}
__device__ __forceinline__ float tanh_fast(float x) {
    float r; asm("tanh.approx.f32 %0, %1;" : "=f"(r) : "f"(x)); return r;
}
__device__ __forceinline__ unsigned smaddr(const void* p) {
    return (unsigned)__cvta_generic_to_shared(p);
}
#define CP16(dst, src) asm volatile("cp.async.cg.shared.global [%0], [%1], 16;" :: "r"(dst), "l"(src))
#define CP_COMMIT()    asm volatile("cp.async.commit_group;" ::: "memory")
#define CP_WAIT0()     asm volatile("cp.async.wait_group 0;" ::: "memory")

// ---------------- edge sort: histogram / scan / scatter -----------------------
__global__ __launch_bounds__(256) void hist_kernel(const int* __restrict__ dst) {
    int e = blockIdx.x * 256 + threadIdx.x;
    atomicAdd(&g_cnt[dst[e]], 1);
}
__global__ __launch_bounds__(256) void scan1_kernel() {
    __shared__ int s[256];
    int i = blockIdx.x * 256 + threadIdx.x;
    int v = (i < N_NODES) ? g_cnt[i] : 0;
    s[threadIdx.x] = v; __syncthreads();
#pragma unroll
    for (int o = 1; o < 256; o <<= 1) {
        int t = (threadIdx.x >= o) ? s[threadIdx.x - o] : 0;
        __syncthreads();
        s[threadIdx.x] += t;
        __syncthreads();
    }
    if (i < N_NODES) g_off[i] = s[threadIdx.x] - v;
    if (threadIdx.x == 255) g_blk[blockIdx.x] = s[255];
}
__global__ __launch_bounds__(256) void scan2_kernel() {
    __shared__ int s[256];
    int v = (threadIdx.x < SCAN_BLKS) ? g_blk[threadIdx.x] : 0;
    s[threadIdx.x] = v; __syncthreads();
#pragma unroll
    for (int o = 1; o < 256; o <<= 1) {
        int t = (threadIdx.x >= o) ? s[threadIdx.x - o] : 0;
        __syncthreads();
        s[threadIdx.x] += t;
        __syncthreads();
    }
    g_blk[threadIdx.x] = s[threadIdx.x] - v;
}
__global__ __launch_bounds__(256) void scan3_kernel() {
    int i = blockIdx.x * 256 + threadIdx.x;
    if (i < N_NODES) {
        int o = g_off[i] + g_blk[blockIdx.x];
        g_off[i] = o;
        g_cnt[i] = o;
    }
}
__global__ __launch_bounds__(256) void scatter_kernel(
    const int* __restrict__ dst, const int* __restrict__ src) {
    int e = blockIdx.x * 256 + threadIdx.x;
    int d = dst[e];
    int slot = atomicAdd(&g_cnt[d], 1);
    g_sdst[slot] = d;
    g_ssrc[slot] = src[e];
    g_perm[slot] = e;
}

// ---------------- conv1: CGConv(C=3, edge=32) -------------------------------
__global__ __launch_bounds__(256) void conv1_kernel(
    const float* __restrict__ x, const int* __restrict__ src, const int* __restrict__ dst,
    const float* __restrict__ eattr,
    const float* __restrict__ Wf, const float* __restrict__ bf,
    const float* __restrict__ Ws, const float* __restrict__ bs,
    float* __restrict__ agg)
{
    __shared__ float wf[38 * 3], ws[38 * 3], bfs[3], bss[3];
    int tid = threadIdx.x;
    if (tid < 114) { wf[tid] = Wf[tid]; ws[tid] = Ws[tid]; }
    if (tid < 3)   { bfs[tid] = bf[tid]; bss[tid] = bs[tid]; }
    __syncthreads();

    int e = blockIdx.x * 256 + tid;
    int d  = dst[e];
    int sn = src[e];

    float f[3], s[3];
#pragma unroll
    for (int j = 0; j < 3; j++) { f[j] = bfs[j]; s[j] = bss[j]; }

#pragma unroll
    for (int i = 0; i < 3; i++) {
        float xd = x[d * 3 + i];
        float xs = x[sn * 3 + i];
#pragma unroll
        for (int j = 0; j < 3; j++) {
            f[j] += xd * wf[i * 3 + j];
            s[j] += xd * ws[i * 3 + j];
            f[j] += xs * wf[(3 + i) * 3 + j];
            s[j] += xs * ws[(3 + i) * 3 + j];
        }
    }
    const float4* ep = (const float4*)(eattr + (size_t)e * 32);
#pragma unroll
    for (int q = 0; q < 8; q++) {
        float4 v = __ldcs(ep + q);
        float ev[4] = {v.x, v.y, v.z, v.w};
#pragma unroll
        for (int r = 0; r < 4; r++) {
            int k = 6 + q * 4 + r;
#pragma unroll
            for (int j = 0; j < 3; j++) {
                f[j] += ev[r] * wf[k * 3 + j];
                s[j] += ev[r] * ws[k * 3 + j];
            }
        }
    }
#pragma unroll
    for (int j = 0; j < 3; j++) {
        float sg = 0.5f + 0.5f * tanh_fast(0.5f * f[j]);
        float sp = fmaxf(s[j], 0.f) + __logf(1.f + __expf(-fabsf(s[j])));
        atomicAdd(agg + (size_t)d * 3 + j, sg * sp);
    }
}

// ---------------- node projection (+ fused fp16 split) ------------------------
__global__ __launch_bounds__(256) void proj_kernel(
    const float* __restrict__ x, const float* __restrict__ agg1,
    const float* __restrict__ Wp, const float* __restrict__ bp,
    float* __restrict__ h, __half* __restrict__ hhi, __half* __restrict__ hlo)
{
    int idx = blockIdx.x * 256 + threadIdx.x;
    int n = idx >> 7, c = idx & 127;
    float v = bp[c];
#pragma unroll
    for (int i = 0; i < 3; i++)
        v += (x[n * 3 + i] + agg1[n * 3 + i]) * Wp[i * 128 + c];
    v = fmaxf(v, 0.f);
    h[idx] = v;
    __half hi = __float2half(v);
    hhi[idx] = hi;
    hlo[idx] = __float2half(v - __half2float(hi));
}

// ---------------- weight pack ---------------------------------------------------
__global__ __launch_bounds__(256) void pack_kernel(
    const float* __restrict__ Wf, const float* __restrict__ Ws,
    __half* __restrict__ Whi, __half* __restrict__ Wlo, __half* __restrict__ WT)
{
    int idx = blockIdx.x * 256 + threadIdx.x;
    {
        int k = idx >> 9;
        int j = idx & 511;
        int role = j >> 8;
        int c = (j & 255) >> 1;
        int gate = j & 1;
        const float* G = gate ? Ws : Wf;
        float v = G[(role * 128 + k) * 128 + c];
        __half hi = __float2half(v);
        Whi[idx] = hi;
        Wlo[idx] = __float2half(v - __half2float(hi));
    }
    if (idx < 256 * 32) {
        int g = idx >> 5;
        int k = idx & 31;
        int c = g >> 1;
        int gate = g & 1;
        const float* G = gate ? Ws : Wf;
        WT[idx] = __float2half(G[(256 + k) * 128 + c]);
    }
}

// ---------------- node GEMM via split-fp16 wmma ------------------------------
__global__ __launch_bounds__(512) void gemm_node(
    const __half* __restrict__ Hhi, const __half* __restrict__ Hlo,
    const __half* __restrict__ Whi, const __half* __restrict__ Wlo,
    __half* __restrict__ A)
{
    extern __shared__ __half sm[];
    __half (*hh)[GPAD] = (__half(*)[GPAD])sm;
    __half (*hl)[GPAD] = hh + 128;
    __half (*wh)[GPAD] = hl + 128;
    __half (*wl)[GPAD] = wh + 128;

    int tid = threadIdx.x;
    int bm = blockIdx.x * 128;
    int bn = blockIdx.y * 128;

#pragma unroll
    for (int t = 0; t < 4; t++) {
        int li = tid + t * 512;
        int row = li >> 4, q = li & 15;
        int rg = bm + row; if (rg > N_NODES - 1) rg = N_NODES - 1;
        CP16(smaddr(&hh[row][q * 8]), Hhi + (size_t)rg * 128 + q * 8);
        CP16(smaddr(&hl[row][q * 8]), Hlo + (size_t)rg * 128 + q * 8);
        CP16(smaddr(&wh[row][q * 8]), Whi + (size_t)row * 512 + bn + q * 8);
        CP16(smaddr(&wl[row][q * 8]), Wlo + (size_t)row * 512 + bn + q * 8);
    }
    CP_COMMIT();
    CP_WAIT0();
    __syncthreads();

    int w  = tid >> 5;
    int mw = w & 7;
    int nh = w >> 3;
    int m0 = mw * 16;

#pragma unroll
    for (int t = 0; t < 4; t++) {
        int n0 = (nh * 4 + t) * 16;
        wmma::fragment<wmma::accumulator, 16, 16, 16, float> acc;
        wmma::fill_fragment(acc, 0.f);
#pragma unroll
        for (int k = 0; k < 8; k++) {
            wmma::fragment<wmma::matrix_a, 16, 16, 16, __half, wmma::row_major> ah, al;
            wmma::fragment<wmma::matrix_b, 16, 16, 16, __half, wmma::row_major> bh, bl;
            wmma::load_matrix_sync(ah, &hh[m0][k * 16], GPAD);
            wmma::load_matrix_sync(al, &hl[m0][k * 16], GPAD);
            wmma::load_matrix_sync(bh, &wh[k * 16][n0], GPAD);
            wmma::load_matrix_sync(bl, &wl[k * 16][n0], GPAD);
            wmma::mma_sync(acc, ah, bh, acc);
            wmma::mma_sync(acc, ah, bl, acc);
            wmma::mma_sync(acc, al, bh, acc);
        }
        wmma::fragment<wmma::accumulator, 16, 16, 16, __half> hacc;
#pragma unroll
        for (int i = 0; i < acc.num_elements; i++) hacc.x[i] = __float2half(acc.x[i]);
        wmma::store_matrix_sync(A + (size_t)(bm + m0) * 512 + bn + n0,
                                hacc, 512, wmma::mem_row_major);
    }
}

// ---- fused CGConv edge kernel (sorted edges, lazy dst, run-combined) ---------
__global__ __launch_bounds__(256) void edge_kernel(
    const int* __restrict__ sdst, const int* __restrict__ ssrc,
    const int* __restrict__ perm,
    const float* __restrict__ eattr,
    const __half* __restrict__ WT,
    const float* __restrict__ bf, const float* __restrict__ bs,
    const uint4* __restrict__ A4, float* __restrict__ agg)
{
    extern __shared__ char smc[];
    __half (*Es)[32]   = (__half(*)[32])smc;                        // 4 KB
    __half (*WTs)[32]  = (__half(*)[32])(smc + 4096);               // 16 KB
    __half (*Ew)[256]  = (__half(*)[256])(smc + 4096 + 16384);      // 32 KB
    int2*  di          = (int2*)(smc + 4096 + 16384 + 32768);       // 512 B

    int tid = threadIdx.x;
    int w   = tid >> 5;
    int l   = tid & 31;
    int ebase = blockIdx.x * 64;

    // gate weights via cp.async (overlaps with the staging below)
    {
        const __half* wsrc = WT + tid * 8;
#pragma unroll
        for (int t = 0; t < 4; t++)
            CP16(smaddr(&WTs[0][0]) + (tid + t * 256) * 16, WT + (size_t)(tid + t * 256) * 8);
    }
    CP_COMMIT();

    if (tid < 64) di[tid] = make_int2(sdst[ebase + tid], ssrc[ebase + tid]);
    {   // edge attrs gathered via perm (each row = one aligned 128B line)
        const float4* b4 = (const float4*)eattr;
#pragma unroll
        for (int t = 0; t < 2; t++) {
            int li = tid + t * 256;          // 0..511
            int e = li >> 3, q = li & 7;
            int pe = __ldg(perm + ebase + e);
            float4 v = __ldcs(b4 + (size_t)pe * 8 + q);
            __half2* dp = (__half2*)&Es[e][q * 4];
            dp[0] = __floats2half2_rn(v.x, v.y);
            dp[1] = __floats2half2_rn(v.z, v.w);
        }
    }
    CP_WAIT0();
    __syncthreads();

    // phase 1: Ew[64][256] = Es @ WT^T  (wmma, fp32 accum)
    {
        int mt = w & 3;
        int nb = (w >> 2) * 8;
        wmma::fragment<wmma::matrix_a, 16, 16, 16, __half, wmma::row_major> a0, a1;
        wmma::load_matrix_sync(a0, &Es[mt * 16][0], 32);
        wmma::load_matrix_sync(a1, &Es[mt * 16][16], 32);
#pragma unroll
        for (int t = 0; t < 8; t++) {
            int nt = nb + t;
            wmma::fragment<wmma::accumulator, 16, 16, 16, float> acc;
            wmma::fill_fragment(acc, 0.f);
            wmma::fragment<wmma::matrix_b, 16, 16, 16, __half, wmma::col_major> b0, b1;
            wmma::load_matrix_sync(b0, &WTs[nt * 16][0], 32);
            wmma::load_matrix_sync(b1, &WTs[nt * 16][16], 32);
            wmma::mma_sync(acc, a0, b0, acc);
            wmma::mma_sync(acc, a1, b1, acc);
            wmma::fragment<wmma::accumulator, 16, 16, 16, __half> hacc;
#pragma unroll
            for (int i = 0; i < acc.num_elements; i++) hacc.x[i] = __float2half(acc.x[i]);
            wmma::store_matrix_sync(&Ew[mt * 16][nt * 16], hacc, 256, wmma::mem_row_major);
        }
    }
    __syncthreads();

    // phase 2: warp-per-edge; per-run fp32 base (bias+dst); fp16 src+gate add
    float4 bf4 = *(const float4*)(bf + 4 * l);
    float4 bs4 = *(const float4*)(bs + 4 * l);
    const float* bfp = (const float*)&bf4;
    const float* bsp = (const float*)&bs4;
    int e0 = w * 8;

    uint4 ps[4];
#pragma unroll
    for (int i = 0; i < 4; i++)
        ps[i] = __ldg(A4 + (size_t)di[e0 + i].y * 64 + 32 + l);

    int cur = di[e0].x;
    float bfd[4], bsd[4];
    {
        uint4 rd = __ldg(A4 + (size_t)cur * 64 + l);
        const __half2* hd = (const __half2*)&rd;
#pragma unroll
        for (int j = 0; j < 4; j++) {
            float2 t = __half22float2(hd[j]);
            bfd[j] = bfp[j] + t.x; bsd[j] = bsp[j] + t.y;
        }
    }
    float facc[4] = {0.f, 0.f, 0.f, 0.f};

#pragma unroll
    for (int i = 0; i < 8; i++) {
        int b = i & 3;
        uint4 rs = ps[b];
        if (i < 4)
            ps[b] = __ldg(A4 + (size_t)di[e0 + i + 4].y * 64 + 32 + l);

        int d = di[e0 + i].x;
        if (d != cur) {                       // warp-uniform
            red_v4(agg + (size_t)cur * 128 + 4 * l, facc[0], facc[1], facc[2], facc[3]);
            cur = d;
            uint4 rd = __ldg(A4 + (size_t)cur * 64 + l);
            const __half2* hd = (const __half2*)&rd;
#pragma unroll
            for (int j = 0; j < 4; j++) {
                float2 t = __half22float2(hd[j]);
                bfd[j] = bfp[j] + t.x; bsd[j] = bsp[j] + t.y;
                facc[j] = 0.f;
            }
        }

        uint4 ewv = *(uint4*)&Ew[e0 + i][8 * l];
        const __half2* hsv = (const __half2*)&rs;
        const __half2* he  = (const __half2*)&ewv;
#pragma unroll
        for (int j = 0; j < 4; j++) {
            __half2 sum = __hadd2(hsv[j], he[j]);      // src + edge gate (fp16)
            float2 t = __half22float2(sum);
            float f = bfd[j] + t.x;
            float s = bsd[j] + t.y;
            float sg = 0.5f + 0.5f * tanh_fast(0.5f * f);
            float sp = fmaxf(s, 0.f) + __logf(1.f + __expf(-fabsf(s)));
            facc[j] += sg * sp;
        }
    }
    red_v4(agg + (size_t)cur * 128 + 4 * l, facc[0], facc[1], facc[2], facc[3]);
}

// ---------------- h = relu(h + agg) + fused fp16 split ------------------------
__global__ __launch_bounds__(256) void relu_add_kernel(
    float4* __restrict__ h, const float4* __restrict__ agg,
    __half2* __restrict__ hhi, __half2* __restrict__ hlo)
{
    int idx = blockIdx.x * 256 + threadIdx.x;
    float4 a = h[idx], b = agg[idx];
    a.x = fmaxf(a.x + b.x, 0.f);
    a.y = fmaxf(a.y + b.y, 0.f);
    a.z = fmaxf(a.z + b.z, 0.f);
    a.w = fmaxf(a.w + b.w, 0.f);
    h[idx] = a;
    __half hx = __float2half(a.x), hy = __float2half(a.y);
    __half hz = __float2half(a.z), hw = __float2half(a.w);
    hhi[idx * 2 + 0] = __halves2half2(hx, hy);
    hhi[idx * 2 + 1] = __halves2half2(hz, hw);
    hlo[idx * 2 + 0] = __halves2half2(__float2half(a.x - __half2float(hx)),
                                      __float2half(a.y - __half2float(hy)));
    hlo[idx * 2 + 1] = __halves2half2(__float2half(a.z - __half2float(hz)),
                                      __float2half(a.w - __half2float(hw)));
}

// ---------------- final relu + mean pool fused (vector RED) -------------------
__global__ __launch_bounds__(256) void relu_pool_kernel(
    const float4* __restrict__ h, const float4* __restrict__ agg,
    const int* __restrict__ batch,
    float* __restrict__ gsum, float* __restrict__ gcnt)
{
    int idx = blockIdx.x * 256 + threadIdx.x;
    int n = idx >> 5, q = idx & 31;
    float4 a = h[idx], b = agg[idx];
    a.x = fmaxf(a.x + b.x, 0.f);
    a.y = fmaxf(a.y + b.y, 0.f);
    a.z = fmaxf(a.z + b.z, 0.f);
    a.w = fmaxf(a.w + b.w, 0.f);
    int g = batch[n];
    red_v4(gsum + (size_t)g * 128 + 4 * q, a.x, a.y, a.z, a.w);
    if (q == 0) atomicAdd(gcnt + g, 1.f);
}

// ---------------- final MLP ---------------------------------------------------
__global__ __launch_bounds__(128) void final_kernel(
    const float* __restrict__ gsum, const float* __restrict__ gcnt,
    const float* __restrict__ W1, const float* __restrict__ b1,
    const float* __restrict__ Wh, const float* __restrict__ bh,
    float* __restrict__ out)
{
    __shared__ float mean[128];
    __shared__ float ga[128];
    int g = blockIdx.x;
    int c = threadIdx.x;
    float cnt = fmaxf(gcnt[g], 1.f);
    mean[c] = gsum[(size_t)g * 128 + c] / cnt;
    __syncthreads();
    float acc = b1[c];
#pragma unroll 8
    for (int k = 0; k < 128; k++)
        acc += mean[k] * W1[k * 128 + c];
    ga[c] = fmaxf(acc, 0.f);
    __syncthreads();
    if (c < 5) {
        float o = bh[c];
#pragma unroll 8
        for (int k = 0; k < 128; k++)
            o += ga[k] * Wh[c * 128 + k];
        out[g * 5 + c] = o;
    }
}

// =============================================================================
extern "C" void kernel_launch(void* const* d_in, const int* in_sizes, int n_in,
                              void* d_out, int out_size)
{
    const float* x        = (const float*)d_in[0];
    const int*   eidx     = (const int*)  d_in[1];
    const float* eattr    = (const float*)d_in[2];
    const int*   batch    = (const int*)  d_in[3];
    const float* Wf1      = (const float*)d_in[4];
    const float* bf1      = (const float*)d_in[5];
    const float* Ws1      = (const float*)d_in[6];
    const float* bs1      = (const float*)d_in[7];
    const float* Wp       = (const float*)d_in[8];
    const float* bp       = (const float*)d_in[9];
    const float* Wf_convs = (const float*)d_in[10];
    const float* bf_convs = (const float*)d_in[11];
    const float* Ws_convs = (const float*)d_in[12];
    const float* bs_convs = (const float*)d_in[13];
    const float* W1       = (const float*)d_in[14];
    const float* b1       = (const float*)d_in[15];
    const float* Wh       = (const float*)d_in[16];
    const float* bh       = (const float*)d_in[17];
    float* out = (float*)d_out;

    const int* srcp = eidx;
    const int* dstp = eidx + N_EDGES;

    float *p_h, *p_agg, *p_gsum, *p_gcnt;
    __half *p_hhi, *p_hlo, *p_A, *p_Whi, *p_Wlo, *p_WT;
    int *p_cnt, *p_sdst, *p_ssrc, *p_perm;
    cudaGetSymbolAddress((void**)&p_h,    g_h);
    cudaGetSymbolAddress((void**)&p_agg,  g_agg);
    cudaGetSymbolAddress((void**)&p_hhi,  g_hhi);
    cudaGetSymbolAddress((void**)&p_hlo,  g_hlo);
    cudaGetSymbolAddress((void**)&p_A,    g_A);
    cudaGetSymbolAddress((void**)&p_Whi,  g_Whi);
    cudaGetSymbolAddress((void**)&p_Wlo,  g_Wlo);
    cudaGetSymbolAddress((void**)&p_WT,   g_WT);
    cudaGetSymbolAddress((void**)&p_gsum, g_gsum);
    cudaGetSymbolAddress((void**)&p_gcnt, g_gcnt);
    cudaGetSymbolAddress((void**)&p_cnt,  g_cnt);
    cudaGetSymbolAddress((void**)&p_sdst, g_sdst);
    cudaGetSymbolAddress((void**)&p_ssrc, g_ssrc);
    cudaGetSymbolAddress((void**)&p_perm, g_perm);

    static cudaStream_t s2 = nullptr;
    static cudaEvent_t ev_root = nullptr, ev_pack = nullptr, ev_sort = nullptr;
    static cudaEvent_t ev_proj = nullptr, ev_ms0 = nullptr, ev_ra = nullptr, ev_ms1 = nullptr;
    static int smem_cfg = 0;
    if (!smem_cfg) {
        cudaFuncSetAttribute(edge_kernel, cudaFuncAttributeMaxDynamicSharedMemorySize, 54272);
        cudaFuncSetAttribute(gemm_node, cudaFuncAttributeMaxDynamicSharedMemorySize, 4 * 128 * GPAD * 2);
        cudaStreamCreateWithFlags(&s2, cudaStreamNonBlocking);
        cudaEventCreateWithFlags(&ev_root, cudaEventDisableTiming);
        cudaEventCreateWithFlags(&ev_pack, cudaEventDisableTiming);
        cudaEventCreateWithFlags(&ev_sort, cudaEventDisableTiming);
        cudaEventCreateWithFlags(&ev_proj, cudaEventDisableTiming);
        cudaEventCreateWithFlags(&ev_ms0,  cudaEventDisableTiming);
        cudaEventCreateWithFlags(&ev_ra,   cudaEventDisableTiming);
        cudaEventCreateWithFlags(&ev_ms1,  cudaEventDisableTiming);
        smem_cfg = 1;
    }

    const int EB  = N_EDGES / 256;                    // 3125
    const int NB  = (N_NODES * HIDDEN) / 256;         // 25000
    const int NB4 = (N_NODES * HIDDEN / 4) / 256;     // 6250
    const int EB2 = N_EDGES / 64;                     // 12500
    const size_t WWSZ = (size_t)128 * 512;
    const size_t WTSZ = (size_t)256 * 32;

    // ---- fork to s2: pack both layers' weights, then the edge sort chain ----
    cudaEventRecord(ev_root, 0);
    cudaStreamWaitEvent(s2, ev_root, 0);
    for (int l = 0; l < 2; l++) {
        pack_kernel<<<(128 * 512) / 256, 256, 0, s2>>>(
            Wf_convs + (size_t)l * 288 * 128, Ws_convs + (size_t)l * 288 * 128,
            p_Whi + l * WWSZ, p_Wlo + l * WWSZ, p_WT + l * WTSZ);
    }
    cudaEventRecord(ev_pack, s2);
    cudaMemsetAsync(p_cnt, 0, N_NODES * sizeof(int), s2);
    hist_kernel<<<EB, 256, 0, s2>>>(dstp);
    scan1_kernel<<<SCAN_BLKS, 256, 0, s2>>>();
    scan2_kernel<<<1, 256, 0, s2>>>();
    scan3_kernel<<<SCAN_BLKS, 256, 0, s2>>>();
    scatter_kernel<<<EB, 256, 0, s2>>>(dstp, srcp);
    cudaEventRecord(ev_sort, s2);

    // ---- main: conv1 + projection ----
    cudaMemsetAsync(p_agg, 0, (size_t)N_NODES * 3 * sizeof(float));
    conv1_kernel<<<EB, 256>>>(x, srcp, dstp, eattr, Wf1, bf1, Ws1, bs1, p_agg);
    proj_kernel<<<NB, 256>>>(x, p_agg, Wp, bp, p_h, p_hhi, p_hlo);
    cudaEventRecord(ev_proj, 0);

    cudaMemsetAsync(p_gsum, 0, (size_t)NUM_GRAPHS * HIDDEN * sizeof(float));
    cudaMemsetAsync(p_gcnt, 0, (size_t)NUM_GRAPHS * sizeof(float));

    // agg memset for layer 0 on s2, overlapped with gemm l0
    cudaStreamWaitEvent(s2, ev_proj, 0);
    cudaMemsetAsync(p_agg, 0, (size_t)N_NODES * HIDDEN * sizeof(float), s2);
    cudaEventRecord(ev_ms0, s2);

    // ---- layer 0 ----
    cudaStreamWaitEvent(0, ev_pack, 0);
    dim3 gg(N_PAD / 128, 4);
    gemm_node<<<gg, 512, 4 * 128 * GPAD * 2>>>(p_hhi, p_hlo, p_Whi, p_Wlo, p_A);
    cudaStreamWaitEvent(0, ev_sort, 0);
    cudaStreamWaitEvent(0, ev_ms0, 0);
    edge_kernel<<<EB2, 256, 54272>>>(p_sdst, p_ssrc, p_perm, eattr,
                                     p_WT, bf_convs, bs_convs,
                                     (const uint4*)p_A, p_agg);
    relu_add_kernel<<<NB4, 256>>>((float4*)p_h, (const float4*)p_agg,
                                  (__half2*)p_hhi, (__half2*)p_hlo);
    cudaEventRecord(ev_ra, 0);

    // agg memset for layer 1 on s2, overlapped with gemm l1
    cudaStreamWaitEvent(s2, ev_ra, 0);
    cudaMemsetAsync(p_agg, 0, (size_t)N_NODES * HIDDEN * sizeof(float), s2);
    cudaEventRecord(ev_ms1, s2);

    // ---- layer 1 ----
    gemm_node<<<gg, 512, 4 * 128 * GPAD * 2>>>(p_hhi, p_hlo,
                                               p_Whi + WWSZ, p_Wlo + WWSZ, p_A);
    cudaStreamWaitEvent(0, ev_ms1, 0);
    edge_kernel<<<EB2, 256, 54272>>>(p_sdst, p_ssrc, p_perm, eattr,
                                     p_WT + WTSZ, bf_convs + 128, bs_convs + 128,
                                     (const uint4*)p_A, p_agg);
    relu_pool_kernel<<<NB4, 256>>>((const float4*)p_h, (const float4*)p_agg,
                                   batch, p_gsum, p_gcnt);

    final_kernel<<<NUM_GRAPHS, 128>>>(p_gsum, p_gcnt, W1, b1, Wh, bh, out);
}

// round 16
// speedup vs baseline: 1.0356x; 1.0025x over previous
#include <cuda_runtime.h>
#include <cuda_fp16.h>
#include <mma.h>
#include <math.h>

using namespace nvcuda;

#define N_NODES   50000
#define N_PAD     50048
#define N_EDGES   800000
#define HIDDEN    128
#define NUM_GRAPHS 256
#define HPAD      40             // 32-halfs chunk row + 8 pad
#define WPAD      136            // 128 + 8 pad
#define SCAN_BLKS 196            // ceil(50000/256)

// ---------------- scratch (device globals) ----------------------------------
__device__ float  g_h[N_NODES * HIDDEN];
__device__ float  g_agg[N_NODES * HIDDEN];
__device__ __half g_hhi[N_NODES * HIDDEN];
__device__ __half g_hlo[N_NODES * HIDDEN];
__device__ __half g_A[(size_t)N_PAD * 512];
__device__ __half g_Whi[2][128 * 512];
__device__ __half g_Wlo[2][128 * 512];
__device__ __half g_WT[2][256 * 32];
__device__ float  g_gsum[NUM_GRAPHS * HIDDEN];
__device__ float  g_gcnt[NUM_GRAPHS];
// edge sort
__device__ int    g_cnt[N_NODES];
__device__ int    g_off[N_NODES];
__device__ int    g_blk[256];
__device__ int    g_perm[N_EDGES];
__device__ int    g_sdst[N_EDGES];
__device__ int    g_ssrc[N_EDGES];

// ---------------- helpers ------------------------------------------------------
__device__ __forceinline__ void red_v4(float* p, float a, float b, float c, float d) {
    asm volatile("red.global.add.v4.f32 [%0], {%1,%2,%3,%4};"
                 :: "l"(p), "f"(a), "f"(b), "f"(c), "f"(d) : "memory");
}
__device__ __forceinline__ float tanh_fast(float x) {
    float r; asm("tanh.approx.f32 %0, %1;" : "=f"(r) : "f"(x)); return r;
}
__device__ __forceinline__ unsigned smaddr(const void* p) {
    return (unsigned)__cvta_generic_to_shared(p);
}
#define CP16(dst, src) asm volatile("cp.async.cg.shared.global [%0], [%1], 16;" :: "r"(dst), "l"(src))
#define CP_COMMIT()    asm volatile("cp.async.commit_group;" ::: "memory")
#define CP_WAIT1()     asm volatile("cp.async.wait_group 1;" ::: "memory")
#define CP_WAIT0()     asm volatile("cp.async.wait_group 0;" ::: "memory")

// ---------------- edge sort: histogram / scan / scatter -----------------------
__global__ __launch_bounds__(256) void hist_kernel(const int* __restrict__ dst) {
    int e = blockIdx.x * 256 + threadIdx.x;
    atomicAdd(&g_cnt[dst[e]], 1);
}
__global__ __launch_bounds__(256) void scan1_kernel() {
    __shared__ int s[256];
    int i = blockIdx.x * 256 + threadIdx.x;
    int v = (i < N_NODES) ? g_cnt[i] : 0;
    s[threadIdx.x] = v; __syncthreads();
#pragma unroll
    for (int o = 1; o < 256; o <<= 1) {
        int t = (threadIdx.x >= o) ? s[threadIdx.x - o] : 0;
        __syncthreads();
        s[threadIdx.x] += t;
        __syncthreads();
    }
    if (i < N_NODES) g_off[i] = s[threadIdx.x] - v;
    if (threadIdx.x == 255) g_blk[blockIdx.x] = s[255];
}
__global__ __launch_bounds__(256) void scan2_kernel() {
    __shared__ int s[256];
    int v = (threadIdx.x < SCAN_BLKS) ? g_blk[threadIdx.x] : 0;
    s[threadIdx.x] = v; __syncthreads();
#pragma unroll
    for (int o = 1; o < 256; o <<= 1) {
        int t = (threadIdx.x >= o) ? s[threadIdx.x - o] : 0;
        __syncthreads();
        s[threadIdx.x] += t;
        __syncthreads();
    }
    g_blk[threadIdx.x] = s[threadIdx.x] - v;
}
__global__ __launch_bounds__(256) void scan3_kernel() {
    int i = blockIdx.x * 256 + threadIdx.x;
    if (i < N_NODES) {
        int o = g_off[i] + g_blk[blockIdx.x];
        g_off[i] = o;
        g_cnt[i] = o;
    }
}
__global__ __launch_bounds__(256) void scatter_kernel(
    const int* __restrict__ dst, const int* __restrict__ src) {
    int e = blockIdx.x * 256 + threadIdx.x;
    int d = dst[e];
    int slot = atomicAdd(&g_cnt[d], 1);
    g_sdst[slot] = d;
    g_ssrc[slot] = src[e];
    g_perm[slot] = e;
}

// ---------------- conv1: CGConv(C=3, edge=32) -------------------------------
__global__ __launch_bounds__(256) void conv1_kernel(
    const float* __restrict__ x, const int* __restrict__ src, const int* __restrict__ dst,
    const float* __restrict__ eattr,
    const float* __restrict__ Wf, const float* __restrict__ bf,
    const float* __restrict__ Ws, const float* __restrict__ bs,
    float* __restrict__ agg)
{
    __shared__ float wf[38 * 3], ws[38 * 3], bfs[3], bss[3];
    int tid = threadIdx.x;
    if (tid < 114) { wf[tid] = Wf[tid]; ws[tid] = Ws[tid]; }
    if (tid < 3)   { bfs[tid] = bf[tid]; bss[tid] = bs[tid]; }
    __syncthreads();

    int e = blockIdx.x * 256 + tid;
    int d  = dst[e];
    int sn = src[e];

    float f[3], s[3];
#pragma unroll
    for (int j = 0; j < 3; j++) { f[j] = bfs[j]; s[j] = bss[j]; }

#pragma unroll
    for (int i = 0; i < 3; i++) {
        float xd = x[d * 3 + i];
        float xs = x[sn * 3 + i];
#pragma unroll
        for (int j = 0; j < 3; j++) {
            f[j] += xd * wf[i * 3 + j];
            s[j] += xd * ws[i * 3 + j];
            f[j] += xs * wf[(3 + i) * 3 + j];
            s[j] += xs * ws[(3 + i) * 3 + j];
        }
    }
    const float4* ep = (const float4*)(eattr + (size_t)e * 32);
#pragma unroll
    for (int q = 0; q < 8; q++) {
        float4 v = __ldcs(ep + q);
        float ev[4] = {v.x, v.y, v.z, v.w};
#pragma unroll
        for (int r = 0; r < 4; r++) {
            int k = 6 + q * 4 + r;
#pragma unroll
            for (int j = 0; j < 3; j++) {
                f[j] += ev[r] * wf[k * 3 + j];
                s[j] += ev[r] * ws[k * 3 + j];
            }
        }
    }
#pragma unroll
    for (int j = 0; j < 3; j++) {
        float sg = 0.5f + 0.5f * tanh_fast(0.5f * f[j]);
        float sp = fmaxf(s[j], 0.f) + __logf(1.f + __expf(-fabsf(s[j])));
        atomicAdd(agg + (size_t)d * 3 + j, sg * sp);
    }
}

// ---------------- node projection (+ fused fp16 split) ------------------------
__global__ __launch_bounds__(256) void proj_kernel(
    const float* __restrict__ x, const float* __restrict__ agg1,
    const float* __restrict__ Wp, const float* __restrict__ bp,
    float* __restrict__ h, __half* __restrict__ hhi, __half* __restrict__ hlo)
{
    int idx = blockIdx.x * 256 + threadIdx.x;
    int n = idx >> 7, c = idx & 127;
    float v = bp[c];
#pragma unroll
    for (int i = 0; i < 3; i++)
        v += (x[n * 3 + i] + agg1[n * 3 + i]) * Wp[i * 128 + c];
    v = fmaxf(v, 0.f);
    h[idx] = v;
    __half hi = __float2half(v);
    hhi[idx] = hi;
    hlo[idx] = __float2half(v - __half2float(hi));
}

// ---------------- weight pack ---------------------------------------------------
__global__ __launch_bounds__(256) void pack_kernel(
    const float* __restrict__ Wf, const float* __restrict__ Ws,
    __half* __restrict__ Whi, __half* __restrict__ Wlo, __half* __restrict__ WT)
{
    int idx = blockIdx.x * 256 + threadIdx.x;
    {
        int k = idx >> 9;
        int j = idx & 511;
        int role = j >> 8;
        int c = (j & 255) >> 1;
        int gate = j & 1;
        const float* G = gate ? Ws : Wf;
        float v = G[(role * 128 + k) * 128 + c];
        __half hi = __float2half(v);
        Whi[idx] = hi;
        Wlo[idx] = __float2half(v - __half2float(hi));
    }
    if (idx < 256 * 32) {
        int g = idx >> 5;
        int k = idx & 31;
        int c = g >> 1;
        int gate = g & 1;
        const float* G = gate ? Ws : Wf;
        WT[idx] = __float2half(G[(256 + k) * 128 + c]);
    }
}

// ------- node GEMM via split-fp16 wmma, K-pipelined double-buffered ----------
__global__ __launch_bounds__(512) void gemm_node(
    const __half* __restrict__ Hhi, const __half* __restrict__ Hlo,
    const __half* __restrict__ Whi, const __half* __restrict__ Wlo,
    __half* __restrict__ A)
{
    extern __shared__ __half sm[];
    // hh[2][128][HPAD], hl[2][128][HPAD], wh[2][32][WPAD], wl[2][32][WPAD]
    __half (*hh)[128][HPAD] = (__half(*)[128][HPAD])sm;
    __half (*hl)[128][HPAD] = hh + 2;
    __half (*wh)[32][WPAD]  = (__half(*)[32][WPAD])(hl + 2);
    __half (*wl)[32][WPAD]  = wh + 2;

    int tid = threadIdx.x;
    int bm = blockIdx.x * 128;
    int bn = blockIdx.y * 128;

    // staging indices (512 threads, one uint4 each per tensor per chunk)
    int hrow = tid >> 2, hq = tid & 3;       // 128 rows x 4 quads of 8 halfs
    int wrow = tid >> 4, wq = tid & 15;      // 32 rows x 16 quads
    int hrg = bm + hrow; if (hrg > N_NODES - 1) hrg = N_NODES - 1;

#define STAGE(b, c) do {                                                          \
        CP16(smaddr(&hh[b][hrow][hq * 8]), Hhi + (size_t)hrg * 128 + (c) * 32 + hq * 8); \
        CP16(smaddr(&hl[b][hrow][hq * 8]), Hlo + (size_t)hrg * 128 + (c) * 32 + hq * 8); \
        CP16(smaddr(&wh[b][wrow][wq * 8]), Whi + (size_t)((c) * 32 + wrow) * 512 + bn + wq * 8); \
        CP16(smaddr(&wl[b][wrow][wq * 8]), Wlo + (size_t)((c) * 32 + wrow) * 512 + bn + wq * 8); \
    } while (0)

    int w  = tid >> 5;
    int mw = w & 7;
    int nh = w >> 3;
    int m0 = mw * 16;

    wmma::fragment<wmma::accumulator, 16, 16, 16, float> acc[4];
#pragma unroll
    for (int t = 0; t < 4; t++) wmma::fill_fragment(acc[t], 0.f);

    STAGE(0, 0);
    CP_COMMIT();

#pragma unroll
    for (int c = 0; c < 4; c++) {
        int buf = c & 1;
        if (c < 3) {
            STAGE(buf ^ 1, c + 1);
            CP_COMMIT();
            CP_WAIT1();
        } else {
            CP_WAIT0();
        }
        __syncthreads();
#pragma unroll
        for (int k2 = 0; k2 < 2; k2++) {
            wmma::fragment<wmma::matrix_a, 16, 16, 16, __half, wmma::row_major> ah, al;
            wmma::load_matrix_sync(ah, &hh[buf][m0][k2 * 16], HPAD);
            wmma::load_matrix_sync(al, &hl[buf][m0][k2 * 16], HPAD);
#pragma unroll
            for (int t = 0; t < 4; t++) {
                int n0 = (nh * 4 + t) * 16;
                wmma::fragment<wmma::matrix_b, 16, 16, 16, __half, wmma::row_major> bh, bl;
                wmma::load_matrix_sync(bh, &wh[buf][k2 * 16][n0], WPAD);
                wmma::load_matrix_sync(bl, &wl[buf][k2 * 16][n0], WPAD);
                wmma::mma_sync(acc[t], ah, bh, acc[t]);
                wmma::mma_sync(acc[t], ah, bl, acc[t]);
                wmma::mma_sync(acc[t], al, bh, acc[t]);
            }
        }
        __syncthreads();
    }
#undef STAGE

#pragma unroll
    for (int t = 0; t < 4; t++) {
        int n0 = (nh * 4 + t) * 16;
        wmma::fragment<wmma::accumulator, 16, 16, 16, __half> hacc;
#pragma unroll
        for (int i = 0; i < hacc.num_elements; i++) hacc.x[i] = __float2half(acc[t].x[i]);
        wmma::store_matrix_sync(A + (size_t)(bm + m0) * 512 + bn + n0,
                                hacc, 512, wmma::mem_row_major);
    }
}

// ---- fused CGConv edge kernel (sorted edges, lazy dst, run-combined) ---------
__global__ __launch_bounds__(256) void edge_kernel(
    const int* __restrict__ sdst, const int* __restrict__ ssrc,
    const int* __restrict__ perm,
    const float* __restrict__ eattr,
    const __half* __restrict__ WT,
    const float* __restrict__ bf, const float* __restrict__ bs,
    const uint4* __restrict__ A4, float* __restrict__ agg)
{
    extern __shared__ char smc[];
    __half (*Es)[32]   = (__half(*)[32])smc;                        // 4 KB
    __half (*WTs)[32]  = (__half(*)[32])(smc + 4096);               // 16 KB
    __half (*Ew)[256]  = (__half(*)[256])(smc + 4096 + 16384);      // 32 KB
    int2*  di          = (int2*)(smc + 4096 + 16384 + 32768);       // 512 B

    int tid = threadIdx.x;
    int w   = tid >> 5;
    int l   = tid & 31;
    int ebase = blockIdx.x * 64;

    // gate weights via cp.async (overlaps with the staging below)
    {
#pragma unroll
        for (int t = 0; t < 4; t++)
            CP16(smaddr(&WTs[0][0]) + (tid + t * 256) * 16, WT + (size_t)(tid + t * 256) * 8);
    }
    CP_COMMIT();

    if (tid < 64) di[tid] = make_int2(sdst[ebase + tid], ssrc[ebase + tid]);
    {   // edge attrs gathered via perm (each row = one aligned 128B line)
        const float4* b4 = (const float4*)eattr;
#pragma unroll
        for (int t = 0; t < 2; t++) {
            int li = tid + t * 256;          // 0..511
            int e = li >> 3, q = li & 7;
            int pe = __ldg(perm + ebase + e);
            float4 v = __ldcs(b4 + (size_t)pe * 8 + q);
            __half2* dp = (__half2*)&Es[e][q * 4];
            dp[0] = __floats2half2_rn(v.x, v.y);
            dp[1] = __floats2half2_rn(v.z, v.w);
        }
    }
    CP_WAIT0();
    __syncthreads();

    // phase 1: Ew[64][256] = Es @ WT^T  (wmma, fp32 accum)
    {
        int mt = w & 3;
        int nb = (w >> 2) * 8;
        wmma::fragment<wmma::matrix_a, 16, 16, 16, __half, wmma::row_major> a0, a1;
        wmma::load_matrix_sync(a0, &Es[mt * 16][0], 32);
        wmma::load_matrix_sync(a1, &Es[mt * 16][16], 32);
#pragma unroll
        for (int t = 0; t < 8; t++) {
            int nt = nb + t;
            wmma::fragment<wmma::accumulator, 16, 16, 16, float> acc;
            wmma::fill_fragment(acc, 0.f);
            wmma::fragment<wmma::matrix_b, 16, 16, 16, __half, wmma::col_major> b0, b1;
            wmma::load_matrix_sync(b0, &WTs[nt * 16][0], 32);
            wmma::load_matrix_sync(b1, &WTs[nt * 16][16], 32);
            wmma::mma_sync(acc, a0, b0, acc);
            wmma::mma_sync(acc, a1, b1, acc);
            wmma::fragment<wmma::accumulator, 16, 16, 16, __half> hacc;
#pragma unroll
            for (int i = 0; i < acc.num_elements; i++) hacc.x[i] = __float2half(acc.x[i]);
            wmma::store_matrix_sync(&Ew[mt * 16][nt * 16], hacc, 256, wmma::mem_row_major);
        }
    }
    __syncthreads();

    // phase 2: warp-per-edge; per-run fp32 base (bias+dst); fp16 src+gate add
    float4 bf4 = *(const float4*)(bf + 4 * l);
    float4 bs4 = *(const float4*)(bs + 4 * l);
    const float* bfp = (const float*)&bf4;
    const float* bsp = (const float*)&bs4;
    int e0 = w * 8;

    uint4 ps[4];
#pragma unroll
    for (int i = 0; i < 4; i++)
        ps[i] = __ldg(A4 + (size_t)di[e0 + i].y * 64 + 32 + l);

    int cur = di[e0].x;
    float bfd[4], bsd[4];
    {
        uint4 rd = __ldg(A4 + (size_t)cur * 64 + l);
        const __half2* hd = (const __half2*)&rd;
#pragma unroll
        for (int j = 0; j < 4; j++) {
            float2 t = __half22float2(hd[j]);
            bfd[j] = bfp[j] + t.x; bsd[j] = bsp[j] + t.y;
        }
    }
    float facc[4] = {0.f, 0.f, 0.f, 0.f};

#pragma unroll
    for (int i = 0; i < 8; i++) {
        int b = i & 3;
        uint4 rs = ps[b];
        if (i < 4)
            ps[b] = __ldg(A4 + (size_t)di[e0 + i + 4].y * 64 + 32 + l);

        int d = di[e0 + i].x;
        if (d != cur) {                       // warp-uniform
            red_v4(agg + (size_t)cur * 128 + 4 * l, facc[0], facc[1], facc[2], facc[3]);
            cur = d;
            uint4 rd = __ldg(A4 + (size_t)cur * 64 + l);
            const __half2* hd = (const __half2*)&rd;
#pragma unroll
            for (int j = 0; j < 4; j++) {
                float2 t = __half22float2(hd[j]);
                bfd[j] = bfp[j] + t.x; bsd[j] = bsp[j] + t.y;
                facc[j] = 0.f;
            }
        }

        uint4 ewv = *(uint4*)&Ew[e0 + i][8 * l];
        const __half2* hsv = (const __half2*)&rs;
        const __half2* he  = (const __half2*)&ewv;
#pragma unroll
        for (int j = 0; j < 4; j++) {
            __half2 sum = __hadd2(hsv[j], he[j]);      // src + edge gate (fp16)
            float2 t = __half22float2(sum);
            float f = bfd[j] + t.x;
            float s = bsd[j] + t.y;
            float sg = 0.5f + 0.5f * tanh_fast(0.5f * f);
            float sp = fmaxf(s, 0.f) + __logf(1.f + __expf(-fabsf(s)));
            facc[j] += sg * sp;
        }
    }
    red_v4(agg + (size_t)cur * 128 + 4 * l, facc[0], facc[1], facc[2], facc[3]);
}

// ---------------- h = relu(h + agg) + fused fp16 split ------------------------
__global__ __launch_bounds__(256) void relu_add_kernel(
    float4* __restrict__ h, const float4* __restrict__ agg,
    __half2* __restrict__ hhi, __half2* __restrict__ hlo)
{
    int idx = blockIdx.x * 256 + threadIdx.x;
    float4 a = h[idx], b = agg[idx];
    a.x = fmaxf(a.x + b.x, 0.f);
    a.y = fmaxf(a.y + b.y, 0.f);
    a.z = fmaxf(a.z + b.z, 0.f);
    a.w = fmaxf(a.w + b.w, 0.f);
    h[idx] = a;
    __half hx = __float2half(a.x), hy = __float2half(a.y);
    __half hz = __float2half(a.z), hw = __float2half(a.w);
    hhi[idx * 2 + 0] = __halves2half2(hx, hy);
    hhi[idx * 2 + 1] = __halves2half2(hz, hw);
    hlo[idx * 2 + 0] = __halves2half2(__float2half(a.x - __half2float(hx)),
                                      __float2half(a.y - __half2float(hy)));
    hlo[idx * 2 + 1] = __halves2half2(__float2half(a.z - __half2float(hz)),
                                      __float2half(a.w - __half2float(hw)));
}

// ---------------- final relu + mean pool fused (vector RED) -------------------
__global__ __launch_bounds__(256) void relu_pool_kernel(
    const float4* __restrict__ h, const float4* __restrict__ agg,
    const int* __restrict__ batch,
    float* __restrict__ gsum, float* __restrict__ gcnt)
{
    int idx = blockIdx.x * 256 + threadIdx.x;
    int n = idx >> 5, q = idx & 31;
    float4 a = h[idx], b = agg[idx];
    a.x = fmaxf(a.x + b.x, 0.f);
    a.y = fmaxf(a.y + b.y, 0.f);
    a.z = fmaxf(a.z + b.z, 0.f);
    a.w = fmaxf(a.w + b.w, 0.f);
    int g = batch[n];
    red_v4(gsum + (size_t)g * 128 + 4 * q, a.x, a.y, a.z, a.w);
    if (q == 0) atomicAdd(gcnt + g, 1.f);
}

// ---------------- final MLP ---------------------------------------------------
__global__ __launch_bounds__(128) void final_kernel(
    const float* __restrict__ gsum, const float* __restrict__ gcnt,
    const float* __restrict__ W1, const float* __restrict__ b1,
    const float* __restrict__ Wh, const float* __restrict__ bh,
    float* __restrict__ out)
{
    __shared__ float mean[128];
    __shared__ float ga[128];
    int g = blockIdx.x;
    int c = threadIdx.x;
    float cnt = fmaxf(gcnt[g], 1.f);
    mean[c] = gsum[(size_t)g * 128 + c] / cnt;
    __syncthreads();
    float acc = b1[c];
#pragma unroll 8
    for (int k = 0; k < 128; k++)
        acc += mean[k] * W1[k * 128 + c];
    ga[c] = fmaxf(acc, 0.f);
    __syncthreads();
    if (c < 5) {
        float o = bh[c];
#pragma unroll 8
        for (int k = 0; k < 128; k++)
            o += ga[k] * Wh[c * 128 + k];
        out[g * 5 + c] = o;
    }
}

// =============================================================================
extern "C" void kernel_launch(void* const* d_in, const int* in_sizes, int n_in,
                              void* d_out, int out_size)
{
    const float* x        = (const float*)d_in[0];
    const int*   eidx     = (const int*)  d_in[1];
    const float* eattr    = (const float*)d_in[2];
    const int*   batch    = (const int*)  d_in[3];
    const float* Wf1      = (const float*)d_in[4];
    const float* bf1      = (const float*)d_in[5];
    const float* Ws1      = (const float*)d_in[6];
    const float* bs1      = (const float*)d_in[7];
    const float* Wp       = (const float*)d_in[8];
    const float* bp       = (const float*)d_in[9];
    const float* Wf_convs = (const float*)d_in[10];
    const float* bf_convs = (const float*)d_in[11];
    const float* Ws_convs = (const float*)d_in[12];
    const float* bs_convs = (const float*)d_in[13];
    const float* W1       = (const float*)d_in[14];
    const float* b1       = (const float*)d_in[15];
    const float* Wh       = (const float*)d_in[16];
    const float* bh       = (const float*)d_in[17];
    float* out = (float*)d_out;

    const int* srcp = eidx;
    const int* dstp = eidx + N_EDGES;

    float *p_h, *p_agg, *p_gsum, *p_gcnt;
    __half *p_hhi, *p_hlo, *p_A, *p_Whi, *p_Wlo, *p_WT;
    int *p_cnt, *p_sdst, *p_ssrc, *p_perm;
    cudaGetSymbolAddress((void**)&p_h,    g_h);
    cudaGetSymbolAddress((void**)&p_agg,  g_agg);
    cudaGetSymbolAddress((void**)&p_hhi,  g_hhi);
    cudaGetSymbolAddress((void**)&p_hlo,  g_hlo);
    cudaGetSymbolAddress((void**)&p_A,    g_A);
    cudaGetSymbolAddress((void**)&p_Whi,  g_Whi);
    cudaGetSymbolAddress((void**)&p_Wlo,  g_Wlo);
    cudaGetSymbolAddress((void**)&p_WT,   g_WT);
    cudaGetSymbolAddress((void**)&p_gsum, g_gsum);
    cudaGetSymbolAddress((void**)&p_gcnt, g_gcnt);
    cudaGetSymbolAddress((void**)&p_cnt,  g_cnt);
    cudaGetSymbolAddress((void**)&p_sdst, g_sdst);
    cudaGetSymbolAddress((void**)&p_ssrc, g_ssrc);
    cudaGetSymbolAddress((void**)&p_perm, g_perm);

    static cudaStream_t s2 = nullptr;
    static cudaEvent_t ev_root = nullptr, ev_pack = nullptr, ev_sort = nullptr;
    static cudaEvent_t ev_proj = nullptr, ev_ms0 = nullptr, ev_ra = nullptr, ev_ms1 = nullptr;
    static int smem_cfg = 0;
    const int GEMM_SMEM = 2 * 128 * HPAD * 2 * 2 + 2 * 32 * WPAD * 2 * 2;  // 75776
    if (!smem_cfg) {
        cudaFuncSetAttribute(edge_kernel, cudaFuncAttributeMaxDynamicSharedMemorySize, 54272);
        cudaFuncSetAttribute(gemm_node, cudaFuncAttributeMaxDynamicSharedMemorySize, GEMM_SMEM);
        cudaStreamCreateWithFlags(&s2, cudaStreamNonBlocking);
        cudaEventCreateWithFlags(&ev_root, cudaEventDisableTiming);
        cudaEventCreateWithFlags(&ev_pack, cudaEventDisableTiming);
        cudaEventCreateWithFlags(&ev_sort, cudaEventDisableTiming);
        cudaEventCreateWithFlags(&ev_proj, cudaEventDisableTiming);
        cudaEventCreateWithFlags(&ev_ms0,  cudaEventDisableTiming);
        cudaEventCreateWithFlags(&ev_ra,   cudaEventDisableTiming);
        cudaEventCreateWithFlags(&ev_ms1,  cudaEventDisableTiming);
        smem_cfg = 1;
    }

    const int EB  = N_EDGES / 256;                    // 3125
    const int NB  = (N_NODES * HIDDEN) / 256;         // 25000
    const int NB4 = (N_NODES * HIDDEN / 4) / 256;     // 6250
    const int EB2 = N_EDGES / 64;                     // 12500
    const size_t WWSZ = (size_t)128 * 512;
    const size_t WTSZ = (size_t)256 * 32;

    // ---- fork to s2: pack both layers' weights, then the edge sort chain ----
    cudaEventRecord(ev_root, 0);
    cudaStreamWaitEvent(s2, ev_root, 0);
    for (int l = 0; l < 2; l++) {
        pack_kernel<<<(128 * 512) / 256, 256, 0, s2>>>(
            Wf_convs + (size_t)l * 288 * 128, Ws_convs + (size_t)l * 288 * 128,
            p_Whi + l * WWSZ, p_Wlo + l * WWSZ, p_WT + l * WTSZ);
    }
    cudaEventRecord(ev_pack, s2);
    cudaMemsetAsync(p_cnt, 0, N_NODES * sizeof(int), s2);
    hist_kernel<<<EB, 256, 0, s2>>>(dstp);
    scan1_kernel<<<SCAN_BLKS, 256, 0, s2>>>();
    scan2_kernel<<<1, 256, 0, s2>>>();
    scan3_kernel<<<SCAN_BLKS, 256, 0, s2>>>();
    scatter_kernel<<<EB, 256, 0, s2>>>(dstp, srcp);
    cudaEventRecord(ev_sort, s2);

    // ---- main: conv1 + projection ----
    cudaMemsetAsync(p_agg, 0, (size_t)N_NODES * 3 * sizeof(float));
    conv1_kernel<<<EB, 256>>>(x, srcp, dstp, eattr, Wf1, bf1, Ws1, bs1, p_agg);
    proj_kernel<<<NB, 256>>>(x, p_agg, Wp, bp, p_h, p_hhi, p_hlo);
    cudaEventRecord(ev_proj, 0);

    cudaMemsetAsync(p_gsum, 0, (size_t)NUM_GRAPHS * HIDDEN * sizeof(float));
    cudaMemsetAsync(p_gcnt, 0, (size_t)NUM_GRAPHS * sizeof(float));

    // agg memset for layer 0 on s2, overlapped with gemm l0
    cudaStreamWaitEvent(s2, ev_proj, 0);
    cudaMemsetAsync(p_agg, 0, (size_t)N_NODES * HIDDEN * sizeof(float), s2);
    cudaEventRecord(ev_ms0, s2);

    // ---- layer 0 ----
    cudaStreamWaitEvent(0, ev_pack, 0);
    dim3 gg(N_PAD / 128, 4);
    gemm_node<<<gg, 512, GEMM_SMEM>>>(p_hhi, p_hlo, p_Whi, p_Wlo, p_A);
    cudaStreamWaitEvent(0, ev_sort, 0);
    cudaStreamWaitEvent(0, ev_ms0, 0);
    edge_kernel<<<EB2, 256, 54272>>>(p_sdst, p_ssrc, p_perm, eattr,
                                     p_WT, bf_convs, bs_convs,
                                     (const uint4*)p_A, p_agg);
    relu_add_kernel<<<NB4, 256>>>((float4*)p_h, (const float4*)p_agg,
                                  (__half2*)p_hhi, (__half2*)p_hlo);
    cudaEventRecord(ev_ra, 0);

    // agg memset for layer 1 on s2, overlapped with gemm l1
    cudaStreamWaitEvent(s2, ev_ra, 0);
    cudaMemsetAsync(p_agg, 0, (size_t)N_NODES * HIDDEN * sizeof(float), s2);
    cudaEventRecord(ev_ms1, s2);

    // ---- layer 1 ----
    gemm_node<<<gg, 512, GEMM_SMEM>>>(p_hhi, p_hlo,
                                      p_Whi + WWSZ, p_Wlo + WWSZ, p_A);
    cudaStreamWaitEvent(0, ev_ms1, 0);
    edge_kernel<<<EB2, 256, 54272>>>(p_sdst, p_ssrc, p_perm, eattr,
                                     p_WT + WTSZ, bf_convs + 128, bs_convs + 128,
                                     (const uint4*)p_A, p_agg);
    relu_pool_kernel<<<NB4, 256>>>((const float4*)p_h, (const float4*)p_agg,
                                   batch, p_gsum, p_gcnt);

    final_kernel<<<NUM_GRAPHS, 128>>>(p_gsum, p_gcnt, W1, b1, Wh, bh, out);
}

// round 17
// speedup vs baseline: 1.0453x; 1.0093x over previous
#include <cuda_runtime.h>
#include <cuda_fp16.h>
#include <mma.h>
#include <math.h>

using namespace nvcuda;

#define N_NODES   50000
#define N_PAD     50048
#define N_EDGES   800000
#define HIDDEN    128
#define NUM_GRAPHS 256
#define HPAD      40             // 32-halfs chunk row + 8 pad
#define WPAD      136            // 128 + 8 pad
#define SCAN_BLKS 196            // ceil(50000/256)

// ---------------- scratch (device globals) ----------------------------------
__device__ float  g_h[N_NODES * HIDDEN];
__device__ float  g_agg[N_NODES * HIDDEN];
__device__ __half g_hhi[N_NODES * HIDDEN];
__device__ __half g_hlo[N_NODES * HIDDEN];
__device__ __half g_A[(size_t)N_PAD * 512];
__device__ __half g_Whi[2][128 * 512];
__device__ __half g_Wlo[2][128 * 512];
__device__ __half g_WT[2][256 * 32];
__device__ float  g_gsum[NUM_GRAPHS * HIDDEN];
__device__ float  g_gcnt[NUM_GRAPHS];
// edge sort
__device__ int    g_cnt[N_NODES];
__device__ int    g_off[N_NODES];
__device__ int    g_blk[256];
__device__ int    g_perm[N_EDGES];
__device__ int    g_sdst[N_EDGES];
__device__ int    g_ssrc[N_EDGES];

// ---------------- helpers ------------------------------------------------------
__device__ __forceinline__ void red_v4(float* p, float a, float b, float c, float d) {
    asm volatile("red.global.add.v4.f32 [%0], {%1,%2,%3,%4};"
                 :: "l"(p), "f"(a), "f"(b), "f"(c), "f"(d) : "memory");
}
__device__ __forceinline__ float tanh_fast(float x) {
    float r; asm("tanh.approx.f32 %0, %1;" : "=f"(r) : "f"(x)); return r;
}
__device__ __forceinline__ unsigned smaddr(const void* p) {
    return (unsigned)__cvta_generic_to_shared(p);
}
#define CP16(dst, src) asm volatile("cp.async.cg.shared.global [%0], [%1], 16;" :: "r"(dst), "l"(src))
#define CP_COMMIT()    asm volatile("cp.async.commit_group;" ::: "memory")
#define CP_WAIT1()     asm volatile("cp.async.wait_group 1;" ::: "memory")
#define CP_WAIT0()     asm volatile("cp.async.wait_group 0;" ::: "memory")

// ---------------- edge sort: histogram / scan / scatter -----------------------
__global__ __launch_bounds__(256) void hist_kernel(const int* __restrict__ dst) {
    int e = blockIdx.x * 256 + threadIdx.x;
    atomicAdd(&g_cnt[dst[e]], 1);
}
__global__ __launch_bounds__(256) void scan1_kernel() {
    __shared__ int s[256];
    int i = blockIdx.x * 256 + threadIdx.x;
    int v = (i < N_NODES) ? g_cnt[i] : 0;
    s[threadIdx.x] = v; __syncthreads();
#pragma unroll
    for (int o = 1; o < 256; o <<= 1) {
        int t = (threadIdx.x >= o) ? s[threadIdx.x - o] : 0;
        __syncthreads();
        s[threadIdx.x] += t;
        __syncthreads();
    }
    if (i < N_NODES) g_off[i] = s[threadIdx.x] - v;
    if (threadIdx.x == 255) g_blk[blockIdx.x] = s[255];
}
__global__ __launch_bounds__(256) void scan2_kernel() {
    __shared__ int s[256];
    int v = (threadIdx.x < SCAN_BLKS) ? g_blk[threadIdx.x] : 0;
    s[threadIdx.x] = v; __syncthreads();
#pragma unroll
    for (int o = 1; o < 256; o <<= 1) {
        int t = (threadIdx.x >= o) ? s[threadIdx.x - o] : 0;
        __syncthreads();
        s[threadIdx.x] += t;
        __syncthreads();
    }
    g_blk[threadIdx.x] = s[threadIdx.x] - v;
}
__global__ __launch_bounds__(256) void scan3_kernel() {
    int i = blockIdx.x * 256 + threadIdx.x;
    if (i < N_NODES) {
        int o = g_off[i] + g_blk[blockIdx.x];
        g_off[i] = o;
        g_cnt[i] = o;
    }
}
__global__ __launch_bounds__(256) void scatter_kernel(
    const int* __restrict__ dst, const int* __restrict__ src) {
    int e = blockIdx.x * 256 + threadIdx.x;
    int d = dst[e];
    int slot = atomicAdd(&g_cnt[d], 1);
    g_sdst[slot] = d;
    g_ssrc[slot] = src[e];
    g_perm[slot] = e;
}

// ---------------- conv1: CGConv(C=3, edge=32) -------------------------------
__global__ __launch_bounds__(256) void conv1_kernel(
    const float* __restrict__ x, const int* __restrict__ src, const int* __restrict__ dst,
    const float* __restrict__ eattr,
    const float* __restrict__ Wf, const float* __restrict__ bf,
    const float* __restrict__ Ws, const float* __restrict__ bs,
    float* __restrict__ agg)
{
    __shared__ float wf[38 * 3], ws[38 * 3], bfs[3], bss[3];
    int tid = threadIdx.x;
    if (tid < 114) { wf[tid] = Wf[tid]; ws[tid] = Ws[tid]; }
    if (tid < 3)   { bfs[tid] = bf[tid]; bss[tid] = bs[tid]; }
    __syncthreads();

    int e = blockIdx.x * 256 + tid;
    int d  = dst[e];
    int sn = src[e];

    float f[3], s[3];
#pragma unroll
    for (int j = 0; j < 3; j++) { f[j] = bfs[j]; s[j] = bss[j]; }

#pragma unroll
    for (int i = 0; i < 3; i++) {
        float xd = x[d * 3 + i];
        float xs = x[sn * 3 + i];
#pragma unroll
        for (int j = 0; j < 3; j++) {
            f[j] += xd * wf[i * 3 + j];
            s[j] += xd * ws[i * 3 + j];
            f[j] += xs * wf[(3 + i) * 3 + j];
            s[j] += xs * ws[(3 + i) * 3 + j];
        }
    }
    const float4* ep = (const float4*)(eattr + (size_t)e * 32);
#pragma unroll
    for (int q = 0; q < 8; q++) {
        float4 v = __ldcs(ep + q);
        float ev[4] = {v.x, v.y, v.z, v.w};
#pragma unroll
        for (int r = 0; r < 4; r++) {
            int k = 6 + q * 4 + r;
#pragma unroll
            for (int j = 0; j < 3; j++) {
                f[j] += ev[r] * wf[k * 3 + j];
                s[j] += ev[r] * ws[k * 3 + j];
            }
        }
    }
#pragma unroll
    for (int j = 0; j < 3; j++) {
        float sg = 0.5f + 0.5f * tanh_fast(0.5f * f[j]);
        float sp = fmaxf(s[j], 0.f) + __logf(1.f + __expf(-fabsf(s[j])));
        atomicAdd(agg + (size_t)d * 3 + j, sg * sp);
    }
}

// ---------------- node projection (+ fused fp16 split) ------------------------
__global__ __launch_bounds__(256) void proj_kernel(
    const float* __restrict__ x, const float* __restrict__ agg1,
    const float* __restrict__ Wp, const float* __restrict__ bp,
    float* __restrict__ h, __half* __restrict__ hhi, __half* __restrict__ hlo)
{
    int idx = blockIdx.x * 256 + threadIdx.x;
    int n = idx >> 7, c = idx & 127;
    float v = bp[c];
#pragma unroll
    for (int i = 0; i < 3; i++)
        v += (x[n * 3 + i] + agg1[n * 3 + i]) * Wp[i * 128 + c];
    v = fmaxf(v, 0.f);
    h[idx] = v;
    __half hi = __float2half(v);
    hhi[idx] = hi;
    hlo[idx] = __float2half(v - __half2float(hi));
}

// ---------------- weight pack ---------------------------------------------------
__global__ __launch_bounds__(256) void pack_kernel(
    const float* __restrict__ Wf, const float* __restrict__ Ws,
    __half* __restrict__ Whi, __half* __restrict__ Wlo, __half* __restrict__ WT)
{
    int idx = blockIdx.x * 256 + threadIdx.x;
    {
        int k = idx >> 9;
        int j = idx & 511;
        int role = j >> 8;
        int c = (j & 255) >> 1;
        int gate = j & 1;
        const float* G = gate ? Ws : Wf;
        float v = G[(role * 128 + k) * 128 + c];
        __half hi = __float2half(v);
        Whi[idx] = hi;
        Wlo[idx] = __float2half(v - __half2float(hi));
    }
    if (idx < 256 * 32) {
        int g = idx >> 5;
        int k = idx & 31;
        int c = g >> 1;
        int gate = g & 1;
        const float* G = gate ? Ws : Wf;
        WT[idx] = __float2half(G[(256 + k) * 128 + c]);
    }
}

// ------- node GEMM via split-fp16 wmma, K-pipelined double-buffered ----------
__global__ __launch_bounds__(512) void gemm_node(
    const __half* __restrict__ Hhi, const __half* __restrict__ Hlo,
    const __half* __restrict__ Whi, const __half* __restrict__ Wlo,
    __half* __restrict__ A)
{
    extern __shared__ __half sm[];
    __half (*hh)[128][HPAD] = (__half(*)[128][HPAD])sm;
    __half (*hl)[128][HPAD] = hh + 2;
    __half (*wh)[32][WPAD]  = (__half(*)[32][WPAD])(hl + 2);
    __half (*wl)[32][WPAD]  = wh + 2;

    int tid = threadIdx.x;
    int bm = blockIdx.x * 128;
    int bn = blockIdx.y * 128;

    int hrow = tid >> 2, hq = tid & 3;
    int wrow = tid >> 4, wq = tid & 15;
    int hrg = bm + hrow; if (hrg > N_NODES - 1) hrg = N_NODES - 1;

#define STAGE(b, c) do {                                                          \
        CP16(smaddr(&hh[b][hrow][hq * 8]), Hhi + (size_t)hrg * 128 + (c) * 32 + hq * 8); \
        CP16(smaddr(&hl[b][hrow][hq * 8]), Hlo + (size_t)hrg * 128 + (c) * 32 + hq * 8); \
        CP16(smaddr(&wh[b][wrow][wq * 8]), Whi + (size_t)((c) * 32 + wrow) * 512 + bn + wq * 8); \
        CP16(smaddr(&wl[b][wrow][wq * 8]), Wlo + (size_t)((c) * 32 + wrow) * 512 + bn + wq * 8); \
    } while (0)

    int w  = tid >> 5;
    int mw = w & 7;
    int nh = w >> 3;
    int m0 = mw * 16;

    wmma::fragment<wmma::accumulator, 16, 16, 16, float> acc[4];
#pragma unroll
    for (int t = 0; t < 4; t++) wmma::fill_fragment(acc[t], 0.f);

    STAGE(0, 0);
    CP_COMMIT();

#pragma unroll
    for (int c = 0; c < 4; c++) {
        int buf = c & 1;
        if (c < 3) {
            STAGE(buf ^ 1, c + 1);
            CP_COMMIT();
            CP_WAIT1();
        } else {
            CP_WAIT0();
        }
        __syncthreads();
#pragma unroll
        for (int k2 = 0; k2 < 2; k2++) {
            wmma::fragment<wmma::matrix_a, 16, 16, 16, __half, wmma::row_major> ah, al;
            wmma::load_matrix_sync(ah, &hh[buf][m0][k2 * 16], HPAD);
            wmma::load_matrix_sync(al, &hl[buf][m0][k2 * 16], HPAD);
#pragma unroll
            for (int t = 0; t < 4; t++) {
                int n0 = (nh * 4 + t) * 16;
                wmma::fragment<wmma::matrix_b, 16, 16, 16, __half, wmma::row_major> bh, bl;
                wmma::load_matrix_sync(bh, &wh[buf][k2 * 16][n0], WPAD);
                wmma::load_matrix_sync(bl, &wl[buf][k2 * 16][n0], WPAD);
                wmma::mma_sync(acc[t], ah, bh, acc[t]);
                wmma::mma_sync(acc[t], ah, bl, acc[t]);
                wmma::mma_sync(acc[t], al, bh, acc[t]);
            }
        }
        __syncthreads();
    }
#undef STAGE

#pragma unroll
    for (int t = 0; t < 4; t++) {
        int n0 = (nh * 4 + t) * 16;
        wmma::fragment<wmma::accumulator, 16, 16, 16, __half> hacc;
#pragma unroll
        for (int i = 0; i < hacc.num_elements; i++) hacc.x[i] = __float2half(acc[t].x[i]);
        wmma::store_matrix_sync(A + (size_t)(bm + m0) * 512 + bn + n0,
                                hacc, 512, wmma::mem_row_major);
    }
}

// ---- fused CGConv edge kernel (sorted edges, dual-dst prefetch, runs) --------
__global__ __launch_bounds__(256) void edge_kernel(
    const int* __restrict__ sdst, const int* __restrict__ ssrc,
    const int* __restrict__ perm,
    const float* __restrict__ eattr,
    const __half* __restrict__ WT,
    const float* __restrict__ bf, const float* __restrict__ bs,
    const uint4* __restrict__ A4, float* __restrict__ agg)
{
    extern __shared__ char smc[];
    __half (*Es)[32]   = (__half(*)[32])smc;                        // 4 KB
    __half (*WTs)[32]  = (__half(*)[32])(smc + 4096);               // 16 KB
    __half (*Ew)[256]  = (__half(*)[256])(smc + 4096 + 16384);      // 32 KB
    int2*  di          = (int2*)(smc + 4096 + 16384 + 32768);       // 512 B

    int tid = threadIdx.x;
    int w   = tid >> 5;
    int l   = tid & 31;
    int ebase = blockIdx.x * 64;

    // gate weights via cp.async (overlaps with the staging below)
    {
#pragma unroll
        for (int t = 0; t < 4; t++)
            CP16(smaddr(&WTs[0][0]) + (tid + t * 256) * 16, WT + (size_t)(tid + t * 256) * 8);
    }
    CP_COMMIT();

    if (tid < 64) di[tid] = make_int2(sdst[ebase + tid], ssrc[ebase + tid]);
    {   // edge attrs gathered via perm (each row = one aligned 128B line)
        const float4* b4 = (const float4*)eattr;
#pragma unroll
        for (int t = 0; t < 2; t++) {
            int li = tid + t * 256;          // 0..511
            int e = li >> 3, q = li & 7;
            int pe = __ldg(perm + ebase + e);
            float4 v = __ldcs(b4 + (size_t)pe * 8 + q);
            __half2* dp = (__half2*)&Es[e][q * 4];
            dp[0] = __floats2half2_rn(v.x, v.y);
            dp[1] = __floats2half2_rn(v.z, v.w);
        }
    }
    CP_WAIT0();
    __syncthreads();

    // phase 1: Ew[64][256] = Es @ WT^T  (wmma, fp32 accum)
    {
        int mt = w & 3;
        int nb = (w >> 2) * 8;
        wmma::fragment<wmma::matrix_a, 16, 16, 16, __half, wmma::row_major> a0, a1;
        wmma::load_matrix_sync(a0, &Es[mt * 16][0], 32);
        wmma::load_matrix_sync(a1, &Es[mt * 16][16], 32);
#pragma unroll
        for (int t = 0; t < 8; t++) {
            int nt = nb + t;
            wmma::fragment<wmma::accumulator, 16, 16, 16, float> acc;
            wmma::fill_fragment(acc, 0.f);
            wmma::fragment<wmma::matrix_b, 16, 16, 16, __half, wmma::col_major> b0, b1;
            wmma::load_matrix_sync(b0, &WTs[nt * 16][0], 32);
            wmma::load_matrix_sync(b1, &WTs[nt * 16][16], 32);
            wmma::mma_sync(acc, a0, b0, acc);
            wmma::mma_sync(acc, a1, b1, acc);
            wmma::fragment<wmma::accumulator, 16, 16, 16, __half> hacc;
#pragma unroll
            for (int i = 0; i < acc.num_elements; i++) hacc.x[i] = __float2half(acc.x[i]);
            wmma::store_matrix_sync(&Ew[mt * 16][nt * 16], hacc, 256, wmma::mem_row_major);
        }
    }
    __syncthreads();

    // phase 2: warp-per-edge; dual boundary-dst prefetch; run-combined RED
    float4 bf4 = *(const float4*)(bf + 4 * l);
    float4 bs4 = *(const float4*)(bs + 4 * l);
    const float* bfp = (const float*)&bf4;
    const float* bsp = (const float*)&bs4;
    int e0 = w * 8;

    uint4 ps[4];
#pragma unroll
    for (int i = 0; i < 4; i++)
        ps[i] = __ldg(A4 + (size_t)di[e0 + i].y * 64 + 32 + l);

    int cur = di[e0].x;
    int d7  = di[e0 + 7].x;
    uint4 rd = __ldg(A4 + (size_t)cur * 64 + l);
    uint4 rd7;
    if (d7 != cur)                              // warp-uniform
        rd7 = __ldg(A4 + (size_t)d7 * 64 + l);

    float bfd[4], bsd[4];
    {
        const __half2* hd = (const __half2*)&rd;
#pragma unroll
        for (int j = 0; j < 4; j++) {
            float2 t = __half22float2(hd[j]);
            bfd[j] = bfp[j] + t.x; bsd[j] = bsp[j] + t.y;
        }
    }
    float facc[4] = {0.f, 0.f, 0.f, 0.f};

#pragma unroll
    for (int i = 0; i < 8; i++) {
        int b = i & 3;
        uint4 rs = ps[b];
        if (i < 4)
            ps[b] = __ldg(A4 + (size_t)di[e0 + i + 4].y * 64 + 32 + l);

        int d = di[e0 + i].x;
        if (d != cur) {                       // warp-uniform
            red_v4(agg + (size_t)cur * 128 + 4 * l, facc[0], facc[1], facc[2], facc[3]);
            cur = d;
            uint4 r = (d == d7) ? rd7 : __ldg(A4 + (size_t)d * 64 + l);
            const __half2* hd = (const __half2*)&r;
#pragma unroll
            for (int j = 0; j < 4; j++) {
                float2 t = __half22float2(hd[j]);
                bfd[j] = bfp[j] + t.x; bsd[j] = bsp[j] + t.y;
                facc[j] = 0.f;
            }
        }

        uint4 ewv = *(uint4*)&Ew[e0 + i][8 * l];
        const __half2* hsv = (const __half2*)&rs;
        const __half2* he  = (const __half2*)&ewv;
#pragma unroll
        for (int j = 0; j < 4; j++) {
            __half2 sum = __hadd2(hsv[j], he[j]);      // src + edge gate (fp16)
            float2 t = __half22float2(sum);
            float f = bfd[j] + t.x;
            float s = bsd[j] + t.y;
            float sg = 0.5f + 0.5f * tanh_fast(0.5f * f);
            float sp = fmaxf(s, 0.f) + __logf(1.f + __expf(-fabsf(s)));
            facc[j] += sg * sp;
        }
    }
    red_v4(agg + (size_t)cur * 128 + 4 * l, facc[0], facc[1], facc[2], facc[3]);
}

// ---------------- h = relu(h + agg) + fused fp16 split ------------------------
__global__ __launch_bounds__(256) void relu_add_kernel(
    float4* __restrict__ h, const float4* __restrict__ agg,
    __half2* __restrict__ hhi, __half2* __restrict__ hlo)
{
    int idx = blockIdx.x * 256 + threadIdx.x;
    float4 a = h[idx], b = agg[idx];
    a.x = fmaxf(a.x + b.x, 0.f);
    a.y = fmaxf(a.y + b.y, 0.f);
    a.z = fmaxf(a.z + b.z, 0.f);
    a.w = fmaxf(a.w + b.w, 0.f);
    h[idx] = a;
    __half hx = __float2half(a.x), hy = __float2half(a.y);
    __half hz = __float2half(a.z), hw = __float2half(a.w);
    hhi[idx * 2 + 0] = __halves2half2(hx, hy);
    hhi[idx * 2 + 1] = __halves2half2(hz, hw);
    hlo[idx * 2 + 0] = __halves2half2(__float2half(a.x - __half2float(hx)),
                                      __float2half(a.y - __half2float(hy)));
    hlo[idx * 2 + 1] = __halves2half2(__float2half(a.z - __half2float(hz)),
                                      __float2half(a.w - __half2float(hw)));
}

// ---------------- final relu + mean pool fused (vector RED) -------------------
__global__ __launch_bounds__(256) void relu_pool_kernel(
    const float4* __restrict__ h, const float4* __restrict__ agg,
    const int* __restrict__ batch,
    float* __restrict__ gsum, float* __restrict__ gcnt)
{
    int idx = blockIdx.x * 256 + threadIdx.x;
    int n = idx >> 5, q = idx & 31;
    float4 a = h[idx], b = agg[idx];
    a.x = fmaxf(a.x + b.x, 0.f);
    a.y = fmaxf(a.y + b.y, 0.f);
    a.z = fmaxf(a.z + b.z, 0.f);
    a.w = fmaxf(a.w + b.w, 0.f);
    int g = batch[n];
    red_v4(gsum + (size_t)g * 128 + 4 * q, a.x, a.y, a.z, a.w);
    if (q == 0) atomicAdd(gcnt + g, 1.f);
}

// ---------------- final MLP ---------------------------------------------------
__global__ __launch_bounds__(128) void final_kernel(
    const float* __restrict__ gsum, const float* __restrict__ gcnt,
    const float* __restrict__ W1, const float* __restrict__ b1,
    const float* __restrict__ Wh, const float* __restrict__ bh,
    float* __restrict__ out)
{
    __shared__ float mean[128];
    __shared__ float ga[128];
    int g = blockIdx.x;
    int c = threadIdx.x;
    float cnt = fmaxf(gcnt[g], 1.f);
    mean[c] = gsum[(size_t)g * 128 + c] / cnt;
    __syncthreads();
    float acc = b1[c];
#pragma unroll 8
    for (int k = 0; k < 128; k++)
        acc += mean[k] * W1[k * 128 + c];
    ga[c] = fmaxf(acc, 0.f);
    __syncthreads();
    if (c < 5) {
        float o = bh[c];
#pragma unroll 8
        for (int k = 0; k < 128; k++)
            o += ga[k] * Wh[c * 128 + k];
        out[g * 5 + c] = o;
    }
}

// =============================================================================
extern "C" void kernel_launch(void* const* d_in, const int* in_sizes, int n_in,
                              void* d_out, int out_size)
{
    const float* x        = (const float*)d_in[0];
    const int*   eidx     = (const int*)  d_in[1];
    const float* eattr    = (const float*)d_in[2];
    const int*   batch    = (const int*)  d_in[3];
    const float* Wf1      = (const float*)d_in[4];
    const float* bf1      = (const float*)d_in[5];
    const float* Ws1      = (const float*)d_in[6];
    const float* bs1      = (const float*)d_in[7];
    const float* Wp       = (const float*)d_in[8];
    const float* bp       = (const float*)d_in[9];
    const float* Wf_convs = (const float*)d_in[10];
    const float* bf_convs = (const float*)d_in[11];
    const float* Ws_convs = (const float*)d_in[12];
    const float* bs_convs = (const float*)d_in[13];
    const float* W1       = (const float*)d_in[14];
    const float* b1       = (const float*)d_in[15];
    const float* Wh       = (const float*)d_in[16];
    const float* bh       = (const float*)d_in[17];
    float* out = (float*)d_out;

    const int* srcp = eidx;
    const int* dstp = eidx + N_EDGES;

    float *p_h, *p_agg, *p_gsum, *p_gcnt;
    __half *p_hhi, *p_hlo, *p_A, *p_Whi, *p_Wlo, *p_WT;
    int *p_cnt, *p_sdst, *p_ssrc, *p_perm;
    cudaGetSymbolAddress((void**)&p_h,    g_h);
    cudaGetSymbolAddress((void**)&p_agg,  g_agg);
    cudaGetSymbolAddress((void**)&p_hhi,  g_hhi);
    cudaGetSymbolAddress((void**)&p_hlo,  g_hlo);
    cudaGetSymbolAddress((void**)&p_A,    g_A);
    cudaGetSymbolAddress((void**)&p_Whi,  g_Whi);
    cudaGetSymbolAddress((void**)&p_Wlo,  g_Wlo);
    cudaGetSymbolAddress((void**)&p_WT,   g_WT);
    cudaGetSymbolAddress((void**)&p_gsum, g_gsum);
    cudaGetSymbolAddress((void**)&p_gcnt, g_gcnt);
    cudaGetSymbolAddress((void**)&p_cnt,  g_cnt);
    cudaGetSymbolAddress((void**)&p_sdst, g_sdst);
    cudaGetSymbolAddress((void**)&p_ssrc, g_ssrc);
    cudaGetSymbolAddress((void**)&p_perm, g_perm);

    static cudaStream_t s2 = nullptr;
    static cudaEvent_t ev_root = nullptr, ev_pack = nullptr, ev_sort = nullptr;
    static cudaEvent_t ev_proj = nullptr, ev_ms0 = nullptr, ev_ra = nullptr, ev_ms1 = nullptr;
    static int smem_cfg = 0;
    const int GEMM_SMEM = 2 * 128 * HPAD * 2 * 2 + 2 * 32 * WPAD * 2 * 2;  // 75776
    if (!smem_cfg) {
        cudaFuncSetAttribute(edge_kernel, cudaFuncAttributeMaxDynamicSharedMemorySize, 54272);
        cudaFuncSetAttribute(gemm_node, cudaFuncAttributeMaxDynamicSharedMemorySize, GEMM_SMEM);
        cudaStreamCreateWithFlags(&s2, cudaStreamNonBlocking);
        cudaEventCreateWithFlags(&ev_root, cudaEventDisableTiming);
        cudaEventCreateWithFlags(&ev_pack, cudaEventDisableTiming);
        cudaEventCreateWithFlags(&ev_sort, cudaEventDisableTiming);
        cudaEventCreateWithFlags(&ev_proj, cudaEventDisableTiming);
        cudaEventCreateWithFlags(&ev_ms0,  cudaEventDisableTiming);
        cudaEventCreateWithFlags(&ev_ra,   cudaEventDisableTiming);
        cudaEventCreateWithFlags(&ev_ms1,  cudaEventDisableTiming);
        smem_cfg = 1;
    }

    const int EB  = N_EDGES / 256;                    // 3125
    const int NB  = (N_NODES * HIDDEN) / 256;         // 25000
    const int NB4 = (N_NODES * HIDDEN / 4) / 256;     // 6250
    const int EB2 = N_EDGES / 64;                     // 12500
    const size_t WWSZ = (size_t)128 * 512;
    const size_t WTSZ = (size_t)256 * 32;

    // ---- fork to s2: pack both layers' weights, then the edge sort chain ----
    cudaEventRecord(ev_root, 0);
    cudaStreamWaitEvent(s2, ev_root, 0);
    for (int l = 0; l < 2; l++) {
        pack_kernel<<<(128 * 512) / 256, 256, 0, s2>>>(
            Wf_convs + (size_t)l * 288 * 128, Ws_convs + (size_t)l * 288 * 128,
            p_Whi + l * WWSZ, p_Wlo + l * WWSZ, p_WT + l * WTSZ);
    }
    cudaEventRecord(ev_pack, s2);
    cudaMemsetAsync(p_cnt, 0, N_NODES * sizeof(int), s2);
    hist_kernel<<<EB, 256, 0, s2>>>(dstp);
    scan1_kernel<<<SCAN_BLKS, 256, 0, s2>>>();
    scan2_kernel<<<1, 256, 0, s2>>>();
    scan3_kernel<<<SCAN_BLKS, 256, 0, s2>>>();
    scatter_kernel<<<EB, 256, 0, s2>>>(dstp, srcp);
    cudaEventRecord(ev_sort, s2);

    // ---- main: conv1 + projection ----
    cudaMemsetAsync(p_agg, 0, (size_t)N_NODES * 3 * sizeof(float));
    conv1_kernel<<<EB, 256>>>(x, srcp, dstp, eattr, Wf1, bf1, Ws1, bs1, p_agg);
    proj_kernel<<<NB, 256>>>(x, p_agg, Wp, bp, p_h, p_hhi, p_hlo);
    cudaEventRecord(ev_proj, 0);

    cudaMemsetAsync(p_gsum, 0, (size_t)NUM_GRAPHS * HIDDEN * sizeof(float));
    cudaMemsetAsync(p_gcnt, 0, (size_t)NUM_GRAPHS * sizeof(float));

    // agg memset for layer 0 on s2, overlapped with gemm l0
    cudaStreamWaitEvent(s2, ev_proj, 0);
    cudaMemsetAsync(p_agg, 0, (size_t)N_NODES * HIDDEN * sizeof(float), s2);
    cudaEventRecord(ev_ms0, s2);

    // ---- layer 0 ----
    cudaStreamWaitEvent(0, ev_pack, 0);
    dim3 gg(N_PAD / 128, 4);
    gemm_node<<<gg, 512, GEMM_SMEM>>>(p_hhi, p_hlo, p_Whi, p_Wlo, p_A);
    cudaStreamWaitEvent(0, ev_sort, 0);
    cudaStreamWaitEvent(0, ev_ms0, 0);
    edge_kernel<<<EB2, 256, 54272>>>(p_sdst, p_ssrc, p_perm, eattr,
                                     p_WT, bf_convs, bs_convs,
                                     (const uint4*)p_A, p_agg);
    relu_add_kernel<<<NB4, 256>>>((float4*)p_h, (const float4*)p_agg,
                                  (__half2*)p_hhi, (__half2*)p_hlo);
    cudaEventRecord(ev_ra, 0);

    // agg memset for layer 1 on s2, overlapped with gemm l1
    cudaStreamWaitEvent(s2, ev_ra, 0);
    cudaMemsetAsync(p_agg, 0, (size_t)N_NODES * HIDDEN * sizeof(float), s2);
    cudaEventRecord(ev_ms1, s2);

    // ---- layer 1 ----
    gemm_node<<<gg, 512, GEMM_SMEM>>>(p_hhi, p_hlo,
                                      p_Whi + WWSZ, p_Wlo + WWSZ, p_A);
    cudaStreamWaitEvent(0, ev_ms1, 0);
    edge_kernel<<<EB2, 256, 54272>>>(p_sdst, p_ssrc, p_perm, eattr,
                                     p_WT + WTSZ, bf_convs + 128, bs_convs + 128,
                                     (const uint4*)p_A, p_agg);
    relu_pool_kernel<<<NB4, 256>>>((const float4*)p_h, (const float4*)p_agg,
                                   batch, p_gsum, p_gcnt);

    final_kernel<<<NUM_GRAPHS, 128>>>(p_gsum, p_gcnt, W1, b1, Wh, bh, out);
}